// round 1
// baseline (speedup 1.0000x reference)
#include <cuda_runtime.h>

#define NENT  100000
#define BATCH 512
#define DD    200
#define FCIN  10368
#define NCH   32
#define EPSBN 1e-5f

__device__ float  g_x0[BATCH * 400];
__device__ float  g_conv[(size_t)BATCH * FCIN];
__device__ float  g_fc[BATCH * DD];
__device__ float  g_xhT[DD * BATCH];
__device__ float  g_a1[NCH];
__device__ float  g_b1[NCH];
__device__ double g_bn1sum[NCH];
__device__ double g_bn1sq[NCH];
__device__ double g_l2[4];
__device__ double g_loss[3];

__device__ __forceinline__ float warp_red(float v) {
#pragma unroll
    for (int o = 16; o > 0; o >>= 1) v += __shfl_down_sync(0xffffffffu, v, o);
    return v;
}

// FMA-only softplus: max(s,0) + log1p(exp(-|s|)).
// exp via 2^n split + degree-6 Taylor; log1p via degree-8 Chebyshev (Clenshaw).
__device__ __forceinline__ float softplus_f(float s) {
    float a = fminf(fabsf(s), 80.0f);
    float y = -a * 1.4426950408889634f;        // -|s| * log2(e)
    float z = y + 12582912.0f;                 // 1.5*2^23 magic round
    int   e = __float_as_int(z) - 0x4B400000;  // round-to-nearest integer
    float n = z - 12582912.0f;
    float f = y - n;                           // f in [-0.5, 0.5]
    float u = f * 0.69314718055994531f;
    float p = 1.38888889e-3f;                  // 1/720
    p = fmaf(p, u, 8.33333333e-3f);            // 1/120
    p = fmaf(p, u, 4.16666667e-2f);            // 1/24
    p = fmaf(p, u, 1.66666667e-1f);            // 1/6
    p = fmaf(p, u, 0.5f);
    p = fmaf(p, u, 1.0f);
    p = fmaf(p, u, 1.0f);
    float sc = __int_as_float((e + 127) << 23);
    float t  = p * sc;                         // exp(-|s|) in (0,1]
    // log1p(t): x = 2t-1 in [-1,1], Clenshaw with Chebyshev coeffs
    float x  = fmaf(2.0f, t, -1.0f);
    float x2 = x + x;
    float b8 = -1.87742e-7f;
    float b7 = fmaf(x2, b8,  1.25054e-6f);
    float b6 = fmaf(x2, b7, -8.50310e-6f)     - b8;
    float b5 = fmaf(x2, b6,  5.94712e-5f)     - b7;
    float b4 = fmaf(x2, b5, -4.33276e-4f)     - b6;
    float b3 = fmaf(x2, b4,  3.36709e-3f)     - b5;
    float b2 = fmaf(x2, b3, -2.94372515e-2f)  - b4;
    float b1 = fmaf(x2, b2,  3.43145751e-1f)  - b3;
    float lp = fmaf(x,  b1,  3.76452813e-1f)  - b2;
    return fmaxf(s, 0.0f) + lp;
}

// ---------------------------------------------------------------- init
__global__ void k_init() {
    int idx = blockIdx.x * blockDim.x + threadIdx.x;
    for (int i = idx; i < BATCH * DD; i += gridDim.x * blockDim.x) g_fc[i] = 0.0f;
    if (idx < NCH) { g_bn1sum[idx] = 0.0; g_bn1sq[idx] = 0.0; }
    if (idx < 4)   g_l2[idx]  = 0.0;
    if (idx < 3)   g_loss[idx] = 0.0;
}

// ------------------------------------------------- gather + embedding L2
__global__ void k_gather(const float* __restrict__ ew, const float* __restrict__ rw,
                         const int* __restrict__ h, const int* __restrict__ r) {
    __shared__ float smh[8], smr[8];
    int b = blockIdx.x, t = threadIdx.x;
    float sh = 0.0f, sr = 0.0f;
    if (t < DD) {
        float v = ew[(size_t)h[b] * DD + t];
        g_x0[b * 400 + t] = v;
        sh = v * v;
        float w = rw[(size_t)r[b] * DD + t];
        g_x0[b * 400 + 200 + t] = w;
        sr = w * w;
    }
    sh = warp_red(sh); sr = warp_red(sr);
    if ((t & 31) == 0) { smh[t >> 5] = sh; smr[t >> 5] = sr; }
    __syncthreads();
    if (t == 0) {
        float H = 0, R = 0;
        for (int i = 0; i < 8; i++) { H += smh[i]; R += smr[i]; }
        atomicAdd(&g_l2[0], (double)H);
        atomicAdd(&g_l2[1], (double)R);
    }
}

// ------------------------------------------------- weight L2 (fc_w + conv_w)
__global__ void k_l2w(const float* __restrict__ fcw, const float* __restrict__ cw) {
    __shared__ float sm[8];
    int t = threadIdx.x;
    float loc = 0.0f;
    for (int i = blockIdx.x * blockDim.x + t; i < DD * FCIN; i += gridDim.x * blockDim.x) {
        float v = fcw[i];
        loc = fmaf(v, v, loc);
    }
    loc = warp_red(loc);
    if ((t & 31) == 0) sm[t >> 5] = loc;
    __syncthreads();
    if (t == 0) {
        float S = 0; for (int i = 0; i < 8; i++) S += sm[i];
        atomicAdd(&g_l2[3], (double)S);
    }
    if (blockIdx.x == 0) {
        __syncthreads();
        float lc = 0.0f;
        if (t < NCH * 9) { float v = cw[t]; lc = v * v; }
        lc = warp_red(lc);
        if ((t & 31) == 0) sm[t >> 5] = lc;
        __syncthreads();
        if (t == 0) {
            float S = 0; for (int i = 0; i < 8; i++) S += sm[i];
            atomicAdd(&g_l2[2], (double)S);
        }
    }
}

// ------------------------------------------------- conv 3x3 + bn1 stats
// bn0 reduces to scaling by g0 (mean/var/shift cancel through bn1); conv_b cancels too.
__global__ void k_conv(const float* __restrict__ cw, const float* __restrict__ g0p) {
    __shared__ float xn[400];
    __shared__ float wts[NCH * 9];
    __shared__ float chs[NCH], chq[NCH];
    int b = blockIdx.x, t = threadIdx.x;
    float g0 = g0p[0];
    if (t < 400) xn[t] = g0 * g_x0[b * 400 + t];
    if (t < NCH * 9) wts[t] = cw[t];
    if (t < NCH) { chs[t] = 0.0f; chq[t] = 0.0f; }
    __syncthreads();
    int p = t;
    bool valid = p < 324;
    int i = valid ? p / 18 : 0;
    int j = valid ? p % 18 : 0;
    const float* base = &xn[i * 20 + j];
    for (int c = 0; c < NCH; c++) {
        float acc = 0.0f;
#pragma unroll
        for (int ki = 0; ki < 3; ki++)
#pragma unroll
            for (int kj = 0; kj < 3; kj++)
                acc = fmaf(base[ki * 20 + kj], wts[c * 9 + ki * 3 + kj], acc);
        if (!valid) acc = 0.0f;
        else g_conv[(size_t)b * FCIN + c * 324 + p] = acc;
        float s = warp_red(acc);
        float q = warp_red(acc * acc);
        if ((t & 31) == 0) { atomicAdd(&chs[c], s); atomicAdd(&chq[c], q); }
    }
    __syncthreads();
    if (t < NCH) {
        atomicAdd(&g_bn1sum[t], (double)chs[t]);
        atomicAdd(&g_bn1sq[t],  (double)chq[t]);
    }
}

// ------------------------------------------------- bn1 finalize
__global__ void k_bn1fin(const float* __restrict__ g1, const float* __restrict__ b1) {
    int t = threadIdx.x;
    if (t < NCH) {
        double cnt = 512.0 * 324.0;
        double mean = g_bn1sum[t] / cnt;
        double var  = g_bn1sq[t] / cnt - mean * mean;
        float a = g1[t] * rsqrtf((float)var + EPSBN);
        g_a1[t] = a;
        g_b1[t] = b1[t] - (float)mean * a;
    }
}

// ------------------------------------------------- FC: y = relu(bn1(conv)) @ fc_w.T
// K split into 8 segments of 1296, float atomics into g_fc.
__global__ __launch_bounds__(256) void k_fc(const float* __restrict__ fcw) {
    __shared__ float As[16][64];
    __shared__ float Bs[16][64];
    int m0 = blockIdx.x * 64;
    int d0 = blockIdx.y * 64;
    int kb = blockIdx.z * 1296;
    int t = threadIdx.x;
    int ty = t >> 4, tx = t & 15;
    int lm = t >> 2, lq = t & 3;
    float acc[4][4];
#pragma unroll
    for (int i = 0; i < 4; i++)
#pragma unroll
        for (int j = 0; j < 4; j++) acc[i][j] = 0.0f;

    for (int ch = 0; ch < 81; ch++) {
        int k4 = kb + ch * 16 + lq * 4;
        float4 av = *(const float4*)&g_conv[(size_t)(m0 + lm) * FCIN + k4];
        int c = k4 / 324;  // 324 % 4 == 0, so channel constant within float4
        float a1 = g_a1[c], b1v = g_b1[c];
        As[lq * 4 + 0][lm] = fmaxf(fmaf(av.x, a1, b1v), 0.0f);
        As[lq * 4 + 1][lm] = fmaxf(fmaf(av.y, a1, b1v), 0.0f);
        As[lq * 4 + 2][lm] = fmaxf(fmaf(av.z, a1, b1v), 0.0f);
        As[lq * 4 + 3][lm] = fmaxf(fmaf(av.w, a1, b1v), 0.0f);
        int dg = d0 + lm;
        float4 bv = make_float4(0.f, 0.f, 0.f, 0.f);
        if (dg < DD) bv = *(const float4*)&fcw[(size_t)dg * FCIN + k4];
        Bs[lq * 4 + 0][lm] = bv.x;
        Bs[lq * 4 + 1][lm] = bv.y;
        Bs[lq * 4 + 2][lm] = bv.z;
        Bs[lq * 4 + 3][lm] = bv.w;
        __syncthreads();
#pragma unroll
        for (int kk = 0; kk < 16; kk++) {
            float4 a = *(const float4*)&As[kk][ty * 4];
            float4 bq = *(const float4*)&Bs[kk][tx * 4];
            float am[4] = {a.x, a.y, a.z, a.w};
            float bm[4] = {bq.x, bq.y, bq.z, bq.w};
#pragma unroll
            for (int i = 0; i < 4; i++)
#pragma unroll
                for (int j = 0; j < 4; j++) acc[i][j] = fmaf(am[i], bm[j], acc[i][j]);
        }
        __syncthreads();
    }
#pragma unroll
    for (int i = 0; i < 4; i++)
#pragma unroll
        for (int j = 0; j < 4; j++) {
            int dg = d0 + tx * 4 + j;
            if (dg < DD) atomicAdd(&g_fc[(m0 + ty * 4 + i) * DD + dg], acc[i][j]);
        }
}

// ------------------------------------------------- bn2 + leaky relu, transpose to [d][b]
__global__ void k_bn2(const float* __restrict__ g2, const float* __restrict__ b2) {
    __shared__ float sms[8], smq[8], par[2];
    int d = blockIdx.x, t = threadIdx.x;
    float y0 = g_fc[t * DD + d];
    float y1 = g_fc[(t + 256) * DD + d];
    float s = y0 + y1;
    float q = fmaf(y0, y0, y1 * y1);
    s = warp_red(s); q = warp_red(q);
    if ((t & 31) == 0) { sms[t >> 5] = s; smq[t >> 5] = q; }
    __syncthreads();
    if (t == 0) {
        float S = 0, Q = 0;
        for (int i = 0; i < 8; i++) { S += sms[i]; Q += smq[i]; }
        float mean = S * (1.0f / 512.0f);
        float var  = Q * (1.0f / 512.0f) - mean * mean;
        float a = g2[d] * rsqrtf(var + EPSBN);
        par[0] = a; par[1] = b2[d] - mean * a;
    }
    __syncthreads();
    float a = par[0], c = par[1];
    float v0 = fmaf(y0, a, c); v0 = v0 > 0.0f ? v0 : 0.01f * v0;
    float v1 = fmaf(y1, a, c); v1 = v1 > 0.0f ? v1 : 0.01f * v1;
    g_xhT[d * BATCH + t] = v0;
    g_xhT[d * BATCH + t + 256] = v1;
}

// ------------------------------------------------- scores GEMM + fused loss
// C[512,100000] = Xh[512,200] @ E.T; never materialized. 128x128 tiles, 8x8/thread.
__global__ __launch_bounds__(256, 2) void k_scores(const float* __restrict__ ew,
                                                   const float* __restrict__ bias,
                                                   const int* __restrict__ pos) {
    __shared__ float Xs[40][128];
    __shared__ float Es[40][132];
    __shared__ float red[3][8];
    int MB = blockIdx.x * 128;   // batch tile (0..3)
    int NB = blockIdx.y * 128;   // entity tile (0..781)
    int t = threadIdx.x, lane = t & 31, w = t >> 5;
    int tx = t & 15, ty = t >> 4;
    int m0 = ty * 8, n0 = tx * 8;
    float acc[8][8];
#pragma unroll
    for (int i = 0; i < 8; i++)
#pragma unroll
        for (int j = 0; j < 8; j++) acc[i][j] = 0.0f;

    int nl = t >> 1;
    int kh = (t & 1) * 20;
    bool evalid = (NB + nl) < NENT;
    const float* erow = ew + (size_t)(NB + nl) * DD + kh;

    for (int ck = 0; ck < 5; ck++) {
        int k0 = ck * 40;
#pragma unroll
        for (int rr = 0; rr < 5; rr++) {
            int kk = rr * 8 + w;
            float4 v = *(const float4*)&g_xhT[(k0 + kk) * BATCH + MB + lane * 4];
            *(float4*)&Xs[kk][lane * 4] = v;
        }
#pragma unroll
        for (int ii = 0; ii < 5; ii++) {
            float4 v = make_float4(0.f, 0.f, 0.f, 0.f);
            if (evalid) v = *(const float4*)&erow[k0 + ii * 4];
            int kk = kh + ii * 4;
            Es[kk + 0][nl] = v.x;
            Es[kk + 1][nl] = v.y;
            Es[kk + 2][nl] = v.z;
            Es[kk + 3][nl] = v.w;
        }
        __syncthreads();
#pragma unroll 10
        for (int kk = 0; kk < 40; kk++) {
            float4 a0 = *(const float4*)&Xs[kk][m0];
            float4 a1 = *(const float4*)&Xs[kk][m0 + 4];
            float4 b0 = *(const float4*)&Es[kk][n0];
            float4 b1 = *(const float4*)&Es[kk][n0 + 4];
            float am[8] = {a0.x, a0.y, a0.z, a0.w, a1.x, a1.y, a1.z, a1.w};
            float bm[8] = {b0.x, b0.y, b0.z, b0.w, b1.x, b1.y, b1.z, b1.w};
#pragma unroll
            for (int i = 0; i < 8; i++)
#pragma unroll
                for (int j = 0; j < 8; j++) acc[i][j] = fmaf(am[i], bm[j], acc[i][j]);
        }
        __syncthreads();
    }

    // epilogue: softplus + score sums + positive-target gather
    float sp = 0.0f, ss = 0.0f, ps = 0.0f;
    int pt[8];
#pragma unroll
    for (int i = 0; i < 8; i++) pt[i] = pos[MB + m0 + i];
#pragma unroll
    for (int j = 0; j < 8; j++) {
        int tg = NB + n0 + j;
        if (tg < NENT) {
            float bv = bias[tg];
#pragma unroll
            for (int i = 0; i < 8; i++) {
                float sv = acc[i][j] + bv;
                sp += softplus_f(sv);
                ss += sv;
                if (tg == pt[i]) ps += sv;
            }
        }
    }
    sp = warp_red(sp); ss = warp_red(ss); ps = warp_red(ps);
    if (lane == 0) { red[0][w] = sp; red[1][w] = ss; red[2][w] = ps; }
    __syncthreads();
    if (t == 0) {
        float SP = 0, SS = 0, PS = 0;
        for (int i = 0; i < 8; i++) { SP += red[0][i]; SS += red[1][i]; PS += red[2][i]; }
        atomicAdd(&g_loss[0], (double)SP);
        atomicAdd(&g_loss[1], (double)SS);
        atomicAdd(&g_loss[2], (double)PS);
    }
}

// ------------------------------------------------- final combine
__global__ void k_final(float* out) {
    double sp = g_loss[0], ss = g_loss[1], ps = g_loss[2];
    double kg = (sp - ss / (double)NENT - 0.9 * ps) / ((double)BATCH * (double)NENT);
    double l2 = g_l2[0] / (2.0 * 512.0 * 200.0)
              + g_l2[1] / (2.0 * 512.0 * 200.0)
              + g_l2[2] / (2.0 * 288.0)
              + g_l2[3] / (2.0 * 200.0);
    out[0] = (float)(kg + 1e-5 * l2);
}

extern "C" void kernel_launch(void* const* d_in, const int* in_sizes, int n_in,
                              void* d_out, int out_size) {
    const float* ew   = (const float*)d_in[0];
    const float* rw   = (const float*)d_in[1];
    const float* cw   = (const float*)d_in[2];
    // d_in[3] conv_b: cancels through bn1
    const float* fcw  = (const float*)d_in[4];
    // d_in[5] fc_b: cancels through bn2
    const float* bias = (const float*)d_in[6];
    const float* g0   = (const float*)d_in[7];
    // d_in[8] bn0_b: cancels through bn1
    const float* g1   = (const float*)d_in[9];
    const float* b1   = (const float*)d_in[10];
    const float* g2   = (const float*)d_in[11];
    const float* b2   = (const float*)d_in[12];
    const int*   h    = (const int*)d_in[13];
    const int*   r    = (const int*)d_in[14];
    const int*   pos  = (const int*)d_in[15];

    k_init<<<100, 256>>>();
    k_gather<<<512, 256>>>(ew, rw, h, r);
    k_l2w<<<256, 256>>>(fcw, cw);
    k_conv<<<512, 352>>>(cw, g0);
    k_bn1fin<<<1, 32>>>(g1, b1);
    k_fc<<<dim3(8, 4, 8), 256>>>(fcw);
    k_bn2<<<200, 256>>>(g2, b2);
    k_scores<<<dim3(4, 782), 256>>>(ew, bias, pos);
    k_final<<<1, 1>>>((float*)d_out);
}

// round 3
// speedup vs baseline: 1.8523x; 1.8523x over previous
#include <cuda_runtime.h>
#include <cuda_bf16.h>
#include <cstdint>

#define NENT  100000
#define BATCH 512
#define DD    200
#define FCIN  10368
#define NCH   32
#define EPSBN 1e-5f
#define KPAD  216            // padded K stride (432B = conflict-free for ldmatrix)

__device__ float          g_x0[BATCH * 400];
__device__ float          g_conv[(size_t)BATCH * FCIN];
__device__ float          g_fc[BATCH * DD];
__device__ __nv_bfloat16  g_xb[BATCH * KPAD];   // padded bf16 X image
__device__ float          g_a1[NCH];
__device__ float          g_b1[NCH];
__device__ double         g_bn1sum[NCH];
__device__ double         g_bn1sq[NCH];
__device__ double         g_l2[4];
__device__ double         g_loss[3];

// ---------------------------------------------------------------- helpers
__device__ __forceinline__ uint32_t smem_u32(const void* p) {
    uint32_t a;
    asm("{ .reg .u64 t; cvta.to.shared.u64 t, %1; cvt.u32.u64 %0, t; }" : "=r"(a) : "l"(p));
    return a;
}

__device__ __forceinline__ void ldm4(uint32_t* r, uint32_t addr) {
    asm volatile("ldmatrix.sync.aligned.m8n8.x4.shared.b16 {%0,%1,%2,%3}, [%4];"
        : "=r"(r[0]), "=r"(r[1]), "=r"(r[2]), "=r"(r[3]) : "r"(addr));
}

__device__ __forceinline__ void mma16816(float* c, const uint32_t* a, const uint32_t* b) {
    asm volatile("mma.sync.aligned.m16n8k16.row.col.f32.bf16.bf16.f32 "
        "{%0,%1,%2,%3}, {%4,%5,%6,%7}, {%8,%9}, {%0,%1,%2,%3};"
        : "+f"(c[0]), "+f"(c[1]), "+f"(c[2]), "+f"(c[3])
        : "r"(a[0]), "r"(a[1]), "r"(a[2]), "r"(a[3]), "r"(b[0]), "r"(b[1]));
}

__device__ __forceinline__ float warp_red(float v) {
#pragma unroll
    for (int o = 16; o > 0; o >>= 1) v += __shfl_down_sync(0xffffffffu, v, o);
    return v;
}

// FMA-only softplus: max(s,0) + log1p(exp(-|s|)).
__device__ __forceinline__ float softplus_f(float s) {
    float a = fminf(fabsf(s), 80.0f);
    float y = -a * 1.4426950408889634f;
    float z = y + 12582912.0f;
    int   e = __float_as_int(z) - 0x4B400000;
    float n = z - 12582912.0f;
    float f = y - n;
    float u = f * 0.69314718055994531f;
    float p = 1.38888889e-3f;
    p = fmaf(p, u, 8.33333333e-3f);
    p = fmaf(p, u, 4.16666667e-2f);
    p = fmaf(p, u, 1.66666667e-1f);
    p = fmaf(p, u, 0.5f);
    p = fmaf(p, u, 1.0f);
    p = fmaf(p, u, 1.0f);
    float sc = __int_as_float((e + 127) << 23);
    float t  = p * sc;
    float x  = fmaf(2.0f, t, -1.0f);
    float x2 = x + x;
    float b8 = -1.87742e-7f;
    float b7 = fmaf(x2, b8,  1.25054e-6f);
    float b6 = fmaf(x2, b7, -8.50310e-6f)     - b8;
    float b5 = fmaf(x2, b6,  5.94712e-5f)     - b7;
    float b4 = fmaf(x2, b5, -4.33276e-4f)     - b6;
    float b3 = fmaf(x2, b4,  3.36709e-3f)     - b5;
    float b2 = fmaf(x2, b3, -2.94372515e-2f)  - b4;
    float b1 = fmaf(x2, b2,  3.43145751e-1f)  - b3;
    float lp = fmaf(x,  b1,  3.76452813e-1f)  - b2;
    return fmaxf(s, 0.0f) + lp;
}

// ---------------------------------------------------------------- init
__global__ void k_init() {
    int idx = blockIdx.x * blockDim.x + threadIdx.x;
    int stride = gridDim.x * blockDim.x;
    for (int i = idx; i < BATCH * DD; i += stride) g_fc[i] = 0.0f;
    uint32_t* xb = (uint32_t*)g_xb;
    for (int i = idx; i < BATCH * KPAD / 2; i += stride) xb[i] = 0u;
    if (idx < NCH) { g_bn1sum[idx] = 0.0; g_bn1sq[idx] = 0.0; }
    if (idx < 4)   g_l2[idx]  = 0.0;
    if (idx < 3)   g_loss[idx] = 0.0;
}

// ------------------------------------------------- gather + embedding L2
__global__ void k_gather(const float* __restrict__ ew, const float* __restrict__ rw,
                         const int* __restrict__ h, const int* __restrict__ r) {
    __shared__ float smh[8], smr[8];
    int b = blockIdx.x, t = threadIdx.x;
    float sh = 0.0f, sr = 0.0f;
    if (t < DD) {
        float v = ew[(size_t)h[b] * DD + t];
        g_x0[b * 400 + t] = v;
        sh = v * v;
        float w = rw[(size_t)r[b] * DD + t];
        g_x0[b * 400 + 200 + t] = w;
        sr = w * w;
    }
    sh = warp_red(sh); sr = warp_red(sr);
    if ((t & 31) == 0) { smh[t >> 5] = sh; smr[t >> 5] = sr; }
    __syncthreads();
    if (t == 0) {
        float H = 0, R = 0;
        for (int i = 0; i < 8; i++) { H += smh[i]; R += smr[i]; }
        atomicAdd(&g_l2[0], (double)H);
        atomicAdd(&g_l2[1], (double)R);
    }
}

// ------------------------------------------------- weight L2 (fc_w + conv_w)
__global__ void k_l2w(const float* __restrict__ fcw, const float* __restrict__ cw) {
    __shared__ float sm[8];
    int t = threadIdx.x;
    float loc = 0.0f;
    for (int i = blockIdx.x * blockDim.x + t; i < DD * FCIN; i += gridDim.x * blockDim.x) {
        float v = fcw[i];
        loc = fmaf(v, v, loc);
    }
    loc = warp_red(loc);
    if ((t & 31) == 0) sm[t >> 5] = loc;
    __syncthreads();
    if (t == 0) {
        float S = 0; for (int i = 0; i < 8; i++) S += sm[i];
        atomicAdd(&g_l2[3], (double)S);
    }
    if (blockIdx.x == 0) {
        __syncthreads();
        float lc = 0.0f;
        if (t < NCH * 9) { float v = cw[t]; lc = v * v; }
        lc = warp_red(lc);
        if ((t & 31) == 0) sm[t >> 5] = lc;
        __syncthreads();
        if (t == 0) {
            float S = 0; for (int i = 0; i < 8; i++) S += sm[i];
            atomicAdd(&g_l2[2], (double)S);
        }
    }
}

// ------------------------------------------------- conv 3x3 + bn1 stats (4 batches/block)
__global__ void k_conv(const float* __restrict__ cw, const float* __restrict__ g0p) {
    __shared__ float xn[4][400];
    __shared__ float wts[NCH * 9];
    __shared__ float chs[NCH], chq[NCH];
    int b0 = blockIdx.x * 4, t = threadIdx.x;
    float g0 = g0p[0];
    for (int i = t; i < 1600; i += 352) xn[i / 400][i % 400] = g0 * g_x0[(b0 + i / 400) * 400 + i % 400];
    if (t < NCH * 9) wts[t] = cw[t];
    if (t < NCH) { chs[t] = 0.0f; chq[t] = 0.0f; }
    __syncthreads();
    bool valid = t < 324;
    int i = valid ? t / 18 : 0;
    int j = valid ? t % 18 : 0;
    int boff = i * 20 + j;
    for (int c = 0; c < NCH; c++) {
        float s = 0.0f, q = 0.0f;
#pragma unroll
        for (int bb = 0; bb < 4; bb++) {
            const float* base = &xn[bb][boff];
            float acc = 0.0f;
#pragma unroll
            for (int ki = 0; ki < 3; ki++)
#pragma unroll
                for (int kj = 0; kj < 3; kj++)
                    acc = fmaf(base[ki * 20 + kj], wts[c * 9 + ki * 3 + kj], acc);
            if (valid) {
                g_conv[(size_t)(b0 + bb) * FCIN + c * 324 + t] = acc;
                s += acc;
                q = fmaf(acc, acc, q);
            }
        }
        s = warp_red(s); q = warp_red(q);
        if ((t & 31) == 0) { atomicAdd(&chs[c], s); atomicAdd(&chq[c], q); }
    }
    __syncthreads();
    if (t < NCH) {
        atomicAdd(&g_bn1sum[t], (double)chs[t]);
        atomicAdd(&g_bn1sq[t],  (double)chq[t]);
    }
}

// ------------------------------------------------- bn1 finalize
__global__ void k_bn1fin(const float* __restrict__ g1, const float* __restrict__ b1) {
    int t = threadIdx.x;
    if (t < NCH) {
        double cnt = 512.0 * 324.0;
        double mean = g_bn1sum[t] / cnt;
        double var  = g_bn1sq[t] / cnt - mean * mean;
        float a = g1[t] * rsqrtf((float)var + EPSBN);
        g_a1[t] = a;
        g_b1[t] = b1[t] - (float)mean * a;
    }
}

// ------------------------------------------------- FC: y = relu(bn1(conv)) @ fc_w.T
__global__ __launch_bounds__(256) void k_fc(const float* __restrict__ fcw) {
    __shared__ float As[16][64];
    __shared__ float Bs[16][64];
    int m0 = blockIdx.x * 64;
    int d0 = blockIdx.y * 64;
    int kb = blockIdx.z * 1296;
    int t = threadIdx.x;
    int ty = t >> 4, tx = t & 15;
    int lm = t >> 2, lq = t & 3;
    float acc[4][4];
#pragma unroll
    for (int i = 0; i < 4; i++)
#pragma unroll
        for (int j = 0; j < 4; j++) acc[i][j] = 0.0f;

    for (int ch = 0; ch < 81; ch++) {
        int k4 = kb + ch * 16 + lq * 4;
        float4 av = *(const float4*)&g_conv[(size_t)(m0 + lm) * FCIN + k4];
        int c = k4 / 324;
        float a1 = g_a1[c], b1v = g_b1[c];
        As[lq * 4 + 0][lm] = fmaxf(fmaf(av.x, a1, b1v), 0.0f);
        As[lq * 4 + 1][lm] = fmaxf(fmaf(av.y, a1, b1v), 0.0f);
        As[lq * 4 + 2][lm] = fmaxf(fmaf(av.z, a1, b1v), 0.0f);
        As[lq * 4 + 3][lm] = fmaxf(fmaf(av.w, a1, b1v), 0.0f);
        int dg = d0 + lm;
        float4 bv = make_float4(0.f, 0.f, 0.f, 0.f);
        if (dg < DD) bv = *(const float4*)&fcw[(size_t)dg * FCIN + k4];
        Bs[lq * 4 + 0][lm] = bv.x;
        Bs[lq * 4 + 1][lm] = bv.y;
        Bs[lq * 4 + 2][lm] = bv.z;
        Bs[lq * 4 + 3][lm] = bv.w;
        __syncthreads();
#pragma unroll
        for (int kk = 0; kk < 16; kk++) {
            float4 a = *(const float4*)&As[kk][ty * 4];
            float4 bq = *(const float4*)&Bs[kk][tx * 4];
            float am[4] = {a.x, a.y, a.z, a.w};
            float bm[4] = {bq.x, bq.y, bq.z, bq.w};
#pragma unroll
            for (int ii = 0; ii < 4; ii++)
#pragma unroll
                for (int jj = 0; jj < 4; jj++) acc[ii][jj] = fmaf(am[ii], bm[jj], acc[ii][jj]);
        }
        __syncthreads();
    }
#pragma unroll
    for (int ii = 0; ii < 4; ii++)
#pragma unroll
        for (int jj = 0; jj < 4; jj++) {
            int dg = d0 + tx * 4 + jj;
            if (dg < DD) atomicAdd(&g_fc[(m0 + ty * 4 + ii) * DD + dg], acc[ii][jj]);
        }
}

// ------------------------------------------------- bn2 + leaky relu -> padded bf16 X image
__global__ void k_bn2(const float* __restrict__ g2, const float* __restrict__ b2) {
    __shared__ float sms[8], smq[8], par[2];
    int d = blockIdx.x, t = threadIdx.x;
    float y0 = g_fc[t * DD + d];
    float y1 = g_fc[(t + 256) * DD + d];
    float s = y0 + y1;
    float q = fmaf(y0, y0, y1 * y1);
    s = warp_red(s); q = warp_red(q);
    if ((t & 31) == 0) { sms[t >> 5] = s; smq[t >> 5] = q; }
    __syncthreads();
    if (t == 0) {
        float S = 0, Q = 0;
        for (int i = 0; i < 8; i++) { S += sms[i]; Q += smq[i]; }
        float mean = S * (1.0f / 512.0f);
        float var  = Q * (1.0f / 512.0f) - mean * mean;
        float a = g2[d] * rsqrtf(var + EPSBN);
        par[0] = a; par[1] = b2[d] - mean * a;
    }
    __syncthreads();
    float a = par[0], c = par[1];
    float v0 = fmaf(y0, a, c); v0 = v0 > 0.0f ? v0 : 0.01f * v0;
    float v1 = fmaf(y1, a, c); v1 = v1 > 0.0f ? v1 : 0.01f * v1;
    g_xb[t * KPAD + d]         = __float2bfloat16_rn(v0);
    g_xb[(t + 256) * KPAD + d] = __float2bfloat16_rn(v1);
}

// ------------------------------------------------- scores: bf16 mma.sync + fused loss
// C[m=batch 128][n=entity 128] per CTA, K=200 (13 k16 steps over padded 208).
// 8 warps in 2x4: warp tile 64(m) x 32(n); 16 mma/warp/kstep; 64 fp32 accums/thread.
__global__ __launch_bounds__(256, 2)
void k_scores(const float* __restrict__ ew, const float* __restrict__ bias,
              const int* __restrict__ pos) {
    extern __shared__ char smem[];
    uint32_t xs = smem_u32(smem);            // X tile: 128 x KPAD bf16 = 55296B
    uint32_t es = xs + 55296;                // E tile: 128 x KPAD bf16 = 55296B
    __shared__ float bsh[128];
    __shared__ int   sposm[128];
    __shared__ float red[3][8];
    int t = threadIdx.x, lane = t & 31, wid = t >> 5;
    int MB = blockIdx.x * 128;   // batch tile
    int NB = blockIdx.y * 128;   // entity tile

    // X tile: straight copy of padded bf16 image slice
    {
        const uint4* src = (const uint4*)(g_xb + MB * KPAD);
        uint4* dst = (uint4*)smem;
        for (int i = t; i < 3456; i += 256) dst[i] = src[i];
    }
    // E tile: fp32 -> bf16 rows (stride 432B)
    char* esm = smem + 55296;
    for (int idx = t; idx < 6400; idx += 256) {
        int row = idx / 50, q = idx % 50;
        int e = NB + row;
        if (e < NENT) {
            float4 v = *(const float4*)&ew[(size_t)e * DD + q * 4];
            uint32_t u0 = ((uint32_t)__bfloat16_as_ushort(__float2bfloat16_rn(v.y)) << 16)
                        |  (uint32_t)__bfloat16_as_ushort(__float2bfloat16_rn(v.x));
            uint32_t u1 = ((uint32_t)__bfloat16_as_ushort(__float2bfloat16_rn(v.w)) << 16)
                        |  (uint32_t)__bfloat16_as_ushort(__float2bfloat16_rn(v.z));
            *(uint2*)(esm + row * 432 + q * 8) = make_uint2(u0, u1);
        }
    }
    // zero pad k = 200..207 for all rows (bytes 400..415)
    for (int idx = t; idx < 512; idx += 256) {
        int row = idx >> 2, c = idx & 3;
        *(uint32_t*)(esm + row * 432 + 400 + c * 4) = 0u;
    }
    if (t < 128) {
        int e = NB + t;
        bsh[t] = (e < NENT) ? bias[e] : 0.0f;
        sposm[t] = pos[MB + t];
    }
    __syncthreads();

    int mw = wid >> 2, nw = wid & 3;
    int m_base = mw * 64, n_base = nw * 32;

    uint32_t aaddr[4], baddr[2];
#pragma unroll
    for (int mt = 0; mt < 4; mt++)
        aaddr[mt] = xs + (uint32_t)(m_base + mt * 16 + (lane & 15)) * 432 + (lane >> 4) * 16;
#pragma unroll
    for (int p = 0; p < 2; p++)
        baddr[p] = es + (uint32_t)(n_base + p * 16 + (lane >> 4) * 8 + (lane & 7)) * 432
                      + ((lane >> 3) & 1) * 16;

    float acc[4][4][4];
#pragma unroll
    for (int i = 0; i < 4; i++)
#pragma unroll
        for (int j = 0; j < 4; j++)
#pragma unroll
            for (int k = 0; k < 4; k++) acc[i][j][k] = 0.0f;

    for (int ks = 0; ks < 13; ks++) {
        uint32_t A[4][4], Bf[2][4];
#pragma unroll
        for (int mt = 0; mt < 4; mt++) ldm4(A[mt], aaddr[mt] + ks * 32);
#pragma unroll
        for (int p = 0; p < 2; p++)   ldm4(Bf[p], baddr[p] + ks * 32);
#pragma unroll
        for (int mt = 0; mt < 4; mt++)
#pragma unroll
            for (int nt = 0; nt < 4; nt++)
                mma16816(acc[mt][nt], A[mt], &Bf[nt >> 1][(nt & 1) * 2]);
    }

    // Epilogue: bias + softplus + three reductions
    float spx = 0.0f, ssx = 0.0f, psx = 0.0f;
#pragma unroll
    for (int mt = 0; mt < 4; mt++) {
        int mrow = m_base + mt * 16 + (lane >> 2);
        int pm0 = sposm[mrow];
        int pm1 = sposm[mrow + 8];
#pragma unroll
        for (int nt = 0; nt < 4; nt++) {
#pragma unroll
            for (int c2 = 0; c2 < 2; c2++) {
                int n = n_base + nt * 8 + (lane & 3) * 2 + c2;
                int e = NB + n;
                if (e < NENT) {
                    float bv = bsh[n];
                    float s0 = acc[mt][nt][c2]     + bv;
                    float s1 = acc[mt][nt][2 + c2] + bv;
                    spx += softplus_f(s0) + softplus_f(s1);
                    ssx += s0 + s1;
                    if (pm0 == e) psx += s0;
                    if (pm1 == e) psx += s1;
                }
            }
        }
    }
    spx = warp_red(spx); ssx = warp_red(ssx); psx = warp_red(psx);
    if (lane == 0) { red[0][wid] = spx; red[1][wid] = ssx; red[2][wid] = psx; }
    __syncthreads();
    if (t == 0) {
        float SP = 0, SS = 0, PS = 0;
        for (int i = 0; i < 8; i++) { SP += red[0][i]; SS += red[1][i]; PS += red[2][i]; }
        atomicAdd(&g_loss[0], (double)SP);
        atomicAdd(&g_loss[1], (double)SS);
        atomicAdd(&g_loss[2], (double)PS);
    }
}

// ------------------------------------------------- final combine
__global__ void k_final(float* out) {
    double sp = g_loss[0], ss = g_loss[1], ps = g_loss[2];
    double kg = (sp - ss / (double)NENT - 0.9 * ps) / ((double)BATCH * (double)NENT);
    double l2 = g_l2[0] / (2.0 * 512.0 * 200.0)
              + g_l2[1] / (2.0 * 512.0 * 200.0)
              + g_l2[2] / (2.0 * 288.0)
              + g_l2[3] / (2.0 * 200.0);
    out[0] = (float)(kg + 1e-5 * l2);
}

extern "C" void kernel_launch(void* const* d_in, const int* in_sizes, int n_in,
                              void* d_out, int out_size) {
    const float* ew   = (const float*)d_in[0];
    const float* rw   = (const float*)d_in[1];
    const float* cw   = (const float*)d_in[2];
    const float* fcw  = (const float*)d_in[4];
    const float* bias = (const float*)d_in[6];
    const float* g0   = (const float*)d_in[7];
    const float* g1   = (const float*)d_in[9];
    const float* b1   = (const float*)d_in[10];
    const float* g2   = (const float*)d_in[11];
    const float* b2   = (const float*)d_in[12];
    const int*   h    = (const int*)d_in[13];
    const int*   r    = (const int*)d_in[14];
    const int*   pos  = (const int*)d_in[15];

    const int SMEM_SC = 2 * 55296;
    cudaFuncSetAttribute(k_scores, cudaFuncAttributeMaxDynamicSharedMemorySize, SMEM_SC);

    k_init<<<100, 256>>>();
    k_gather<<<512, 256>>>(ew, rw, h, r);
    k_l2w<<<256, 256>>>(fcw, cw);
    k_conv<<<128, 352>>>(cw, g0);
    k_bn1fin<<<1, 32>>>(g1, b1);
    k_fc<<<dim3(8, 4, 8), 256>>>(fcw);
    k_bn2<<<200, 256>>>(g2, b2);
    k_scores<<<dim3(4, 782), 256, SMEM_SC>>>(ew, bias, pos);
    k_final<<<1, 1>>>((float*)d_out);
}

// round 4
// speedup vs baseline: 2.3602x; 1.2742x over previous
#include <cuda_runtime.h>
#include <cuda_bf16.h>
#include <cstdint>

#define NENT  100000
#define BATCH 512
#define DD    200
#define FCIN  10368
#define NCH   32
#define EPSBN 1e-5f
#define KPAD  216            // padded K stride for X image (432B rows)

__device__ float          g_conv[(size_t)BATCH * FCIN];
__device__ float          g_fc[BATCH * DD];
__device__ __nv_bfloat16  g_xb[BATCH * KPAD];          // padded bf16 X image
__device__ __nv_bfloat16  g_fcb[208 * FCIN];           // bf16 fc_w, d-padded
__device__ float          g_a1[NCH];
__device__ float          g_b1[NCH];
__device__ double         g_bn1sum[NCH];
__device__ double         g_bn1sq[NCH];
__device__ double         g_l2[4];
__device__ double         g_loss[3];

// ---------------------------------------------------------------- helpers
__device__ __forceinline__ uint32_t smem_u32(const void* p) {
    uint32_t a;
    asm("{ .reg .u64 t; cvta.to.shared.u64 t, %1; cvt.u32.u64 %0, t; }" : "=r"(a) : "l"(p));
    return a;
}
__device__ __forceinline__ void ldm4(uint32_t* r, uint32_t addr) {
    asm volatile("ldmatrix.sync.aligned.m8n8.x4.shared.b16 {%0,%1,%2,%3}, [%4];"
        : "=r"(r[0]), "=r"(r[1]), "=r"(r[2]), "=r"(r[3]) : "r"(addr));
}
__device__ __forceinline__ void mma16816(float* c, const uint32_t* a, const uint32_t* b) {
    asm volatile("mma.sync.aligned.m16n8k16.row.col.f32.bf16.bf16.f32 "
        "{%0,%1,%2,%3}, {%4,%5,%6,%7}, {%8,%9}, {%0,%1,%2,%3};"
        : "+f"(c[0]), "+f"(c[1]), "+f"(c[2]), "+f"(c[3])
        : "r"(a[0]), "r"(a[1]), "r"(a[2]), "r"(a[3]), "r"(b[0]), "r"(b[1]));
}
__device__ __forceinline__ float warp_red(float v) {
#pragma unroll
    for (int o = 16; o > 0; o >>= 1) v += __shfl_down_sync(0xffffffffu, v, o);
    return v;
}
// MUFU softplus: max(s,0) + ln2*lg2(1 + 2^(-|s|*log2e))
__device__ __forceinline__ float softplus_fast(float s) {
    float e, l;
    float xn = -fabsf(s) * 1.4426950408889634f;
    asm("ex2.approx.f32 %0, %1;" : "=f"(e) : "f"(xn));
    float arg = 1.0f + e;
    asm("lg2.approx.f32 %0, %1;" : "=f"(l) : "f"(arg));
    return fmaxf(s, 0.0f) + 0.69314718055994531f * l;
}

// ---------------------------------------------------------------- init
__global__ void k_init() {
    int idx = blockIdx.x * blockDim.x + threadIdx.x;
    int stride = gridDim.x * blockDim.x;
    for (int i = idx; i < BATCH * DD; i += stride) g_fc[i] = 0.0f;
    uint32_t* xb = (uint32_t*)g_xb;
    for (int i = idx; i < BATCH * KPAD / 2; i += stride) xb[i] = 0u;
    uint32_t* fp = (uint32_t*)(g_fcb + 200 * FCIN);
    for (int i = idx; i < 8 * FCIN / 2; i += stride) fp[i] = 0u;
    if (idx < NCH) { g_bn1sum[idx] = 0.0; g_bn1sq[idx] = 0.0; }
    if (idx < 4)   g_l2[idx]  = 0.0;
    if (idx < 3)   g_loss[idx] = 0.0;
}

// ------------------------------------------------- fcw L2 + bf16 convert; conv_w L2
__global__ void k_l2w(const float* __restrict__ fcw, const float* __restrict__ cw) {
    __shared__ float sm[8];
    int t = threadIdx.x;
    float loc = 0.0f;
    for (int i = blockIdx.x * blockDim.x + t; i < DD * FCIN; i += gridDim.x * blockDim.x) {
        float v = fcw[i];
        loc = fmaf(v, v, loc);
        g_fcb[i] = __float2bfloat16_rn(v);
    }
    loc = warp_red(loc);
    if ((t & 31) == 0) sm[t >> 5] = loc;
    __syncthreads();
    if (t == 0) {
        float S = 0; for (int i = 0; i < 8; i++) S += sm[i];
        atomicAdd(&g_l2[3], (double)S);
    }
    if (blockIdx.x == 0) {
        __syncthreads();
        float lc = 0.0f;
        if (t < NCH * 9) { float v = cw[t]; lc = v * v; }
        lc = warp_red(lc);
        if ((t & 31) == 0) sm[t >> 5] = lc;
        __syncthreads();
        if (t == 0) {
            float S = 0; for (int i = 0; i < 8; i++) S += sm[i];
            atomicAdd(&g_l2[2], (double)S);
        }
    }
}

// ------------------------------------------------- fused gather + emb L2 + conv (no stats)
__global__ void k_conv(const float* __restrict__ ew, const float* __restrict__ rw,
                       const int* __restrict__ h, const int* __restrict__ r,
                       const float* __restrict__ cw, const float* __restrict__ g0p) {
    __shared__ float xn[4][400];
    __shared__ float wts[NCH * 9];
    __shared__ float shh[11], shr[11];
    int b0 = blockIdx.x * 4, t = threadIdx.x;
    float g0 = g0p[0];
    float l2h = 0.0f, l2r = 0.0f;
    for (int i = t; i < 1600; i += 352) {
        int bb = i / 400, pos = i % 400, b = b0 + bb;
        float v;
        if (pos < 200) { v = ew[(size_t)h[b] * DD + pos]; l2h = fmaf(v, v, l2h); }
        else           { v = rw[(size_t)r[b] * DD + (pos - 200)]; l2r = fmaf(v, v, l2r); }
        xn[bb][pos] = g0 * v;
    }
    if (t < NCH * 9) wts[t] = cw[t];
    l2h = warp_red(l2h); l2r = warp_red(l2r);
    if ((t & 31) == 0) { shh[t >> 5] = l2h; shr[t >> 5] = l2r; }
    __syncthreads();
    if (t == 0) {
        float H = 0, R = 0;
        for (int i = 0; i < 11; i++) { H += shh[i]; R += shr[i]; }
        atomicAdd(&g_l2[0], (double)H);
        atomicAdd(&g_l2[1], (double)R);
    }
    if (t < 324) {
        int i = t / 18, j = t % 18;
        int boff = i * 20 + j;
        for (int c = 0; c < NCH; c++) {
#pragma unroll
            for (int bb = 0; bb < 4; bb++) {
                const float* base = &xn[bb][boff];
                float acc = 0.0f;
#pragma unroll
                for (int ki = 0; ki < 3; ki++)
#pragma unroll
                    for (int kj = 0; kj < 3; kj++)
                        acc = fmaf(base[ki * 20 + kj], wts[c * 9 + ki * 3 + kj], acc);
                g_conv[(size_t)(b0 + bb) * FCIN + c * 324 + t] = acc;
            }
        }
    }
}

// ------------------------------------------------- bn1 stats: stream g_conv
__global__ void k_bn1stats() {
    __shared__ float sms[8], smq[8];
    int c = blockIdx.x, sl = blockIdx.y, t = threadIdx.x;
    float s = 0.0f, q = 0.0f;
    for (int bb = 0; bb < 64; bb++) {
        const float* p = &g_conv[(size_t)(sl * 64 + bb) * FCIN + c * 324];
        for (int i = t; i < 324; i += 256) { float v = p[i]; s += v; q = fmaf(v, v, q); }
    }
    s = warp_red(s); q = warp_red(q);
    if ((t & 31) == 0) { sms[t >> 5] = s; smq[t >> 5] = q; }
    __syncthreads();
    if (t == 0) {
        float S = 0, Q = 0;
        for (int i = 0; i < 8; i++) { S += sms[i]; Q += smq[i]; }
        atomicAdd(&g_bn1sum[c], (double)S);
        atomicAdd(&g_bn1sq[c],  (double)Q);
    }
}

// ------------------------------------------------- bn1 finalize
__global__ void k_bn1fin(const float* __restrict__ g1, const float* __restrict__ b1) {
    int t = threadIdx.x;
    if (t < NCH) {
        double cnt = 512.0 * 324.0;
        double mean = g_bn1sum[t] / cnt;
        double var  = g_bn1sq[t] / cnt - mean * mean;
        float a = g1[t] * rsqrtf((float)var + EPSBN);
        g_a1[t] = a;
        g_b1[t] = b1[t] - (float)mean * a;
    }
}

// ------------------------------------------------- FC via bf16 mma: g_fc += relu(bn1(conv)) @ fcw^T
// grid (4 m-tiles of 128 batch, 2 n-tiles of 128 d, 9 k-segments of 1152).
// 8 warps 2x4: warp 64m x 32n. K chunks of 64, smem stride 144B.
__global__ __launch_bounds__(256, 2) void k_fc() {
    __shared__ __align__(16) char As[128 * 144];
    __shared__ __align__(16) char Bs[128 * 144];
    __shared__ float a_tab[64], b_tab[64];
    uint32_t as_ = smem_u32(As), bs_ = smem_u32(Bs);
    int t = threadIdx.x, lane = t & 31, wid = t >> 5;
    int m0 = blockIdx.x * 128, n0 = blockIdx.y * 128;
    int kseg = blockIdx.z * 1152;

    int mw = wid >> 2, nw = wid & 3;
    int m_base = mw * 64, n_base = nw * 32;
    uint32_t aaddr[4], baddr[2];
#pragma unroll
    for (int mt = 0; mt < 4; mt++)
        aaddr[mt] = as_ + (uint32_t)(m_base + mt * 16 + (lane & 15)) * 144 + (lane >> 4) * 16;
#pragma unroll
    for (int p = 0; p < 2; p++)
        baddr[p] = bs_ + (uint32_t)(n_base + p * 16 + (lane >> 4) * 8 + (lane & 7)) * 144
                       + ((lane >> 3) & 1) * 16;

    float acc[4][4][4];
#pragma unroll
    for (int i = 0; i < 4; i++)
#pragma unroll
        for (int j = 0; j < 4; j++)
#pragma unroll
            for (int k = 0; k < 4; k++) acc[i][j][k] = 0.0f;

    for (int ch = 0; ch < 18; ch++) {
        int kb = kseg + ch * 64;
        if (t < 64) {
            int c = (kb + t) / 324;
            a_tab[t] = g_a1[c];
            b_tab[t] = g_b1[c];
        }
        __syncthreads();   // a_tab ready before A pack (also guards smem reuse)
        // A: 128 rows x 64 k, apply affine+relu, cvt bf16
        {
            int row = t >> 1, half = t & 1;
            const float* src = &g_conv[(size_t)(m0 + row) * FCIN + kb];
#pragma unroll
            for (int j = 0; j < 8; j++) {
                int kc = half * 32 + j * 4;
                float4 v = *(const float4*)&src[kc];
                float y0 = fmaxf(fmaf(v.x, a_tab[kc],     b_tab[kc]),     0.0f);
                float y1 = fmaxf(fmaf(v.y, a_tab[kc + 1], b_tab[kc + 1]), 0.0f);
                float y2 = fmaxf(fmaf(v.z, a_tab[kc + 2], b_tab[kc + 2]), 0.0f);
                float y3 = fmaxf(fmaf(v.w, a_tab[kc + 3], b_tab[kc + 3]), 0.0f);
                uint32_t u0 = ((uint32_t)__bfloat16_as_ushort(__float2bfloat16_rn(y1)) << 16)
                            |  (uint32_t)__bfloat16_as_ushort(__float2bfloat16_rn(y0));
                uint32_t u1 = ((uint32_t)__bfloat16_as_ushort(__float2bfloat16_rn(y3)) << 16)
                            |  (uint32_t)__bfloat16_as_ushort(__float2bfloat16_rn(y2));
                *(uint2*)&As[row * 144 + kc * 2] = make_uint2(u0, u1);
            }
        }
        // B: 128 rows (d) x 64 k from pre-converted g_fcb
        {
#pragma unroll
            for (int j = 0; j < 2; j++) {
                int id = t + j * 256;
                int row = id >> 2, off = (id & 3) * 16;
                int d = n0 + row;
                uint4 v0 = make_uint4(0, 0, 0, 0), v1 = make_uint4(0, 0, 0, 0);
                if (d < 208) {
                    const uint4* src = (const uint4*)&g_fcb[(size_t)d * FCIN + kb + off];
                    v0 = src[0]; v1 = src[1];
                }
                uint4* dst = (uint4*)&Bs[row * 144 + off * 2];
                dst[0] = v0; dst[1] = v1;
            }
        }
        __syncthreads();
#pragma unroll
        for (int ks = 0; ks < 4; ks++) {
            uint32_t A[4][4], Bf[2][4];
#pragma unroll
            for (int mt = 0; mt < 4; mt++) ldm4(A[mt], aaddr[mt] + ks * 32);
#pragma unroll
            for (int p = 0; p < 2; p++)   ldm4(Bf[p], baddr[p] + ks * 32);
#pragma unroll
            for (int mt = 0; mt < 4; mt++)
#pragma unroll
                for (int nt = 0; nt < 4; nt++)
                    mma16816(acc[mt][nt], A[mt], &Bf[nt >> 1][(nt & 1) * 2]);
        }
        __syncthreads();
    }
    // epilogue: atomic accumulate into g_fc
#pragma unroll
    for (int mt = 0; mt < 4; mt++) {
        int r0 = m0 + m_base + mt * 16 + (lane >> 2);
#pragma unroll
        for (int nt = 0; nt < 4; nt++) {
#pragma unroll
            for (int c2 = 0; c2 < 2; c2++) {
                int d = n0 + n_base + nt * 8 + (lane & 3) * 2 + c2;
                if (d < DD) {
                    atomicAdd(&g_fc[r0 * DD + d],       acc[mt][nt][c2]);
                    atomicAdd(&g_fc[(r0 + 8) * DD + d], acc[mt][nt][2 + c2]);
                }
            }
        }
    }
}

// ------------------------------------------------- bn2 + leaky relu -> padded bf16 X image
__global__ void k_bn2(const float* __restrict__ g2, const float* __restrict__ b2) {
    __shared__ float sms[8], smq[8], par[2];
    int d = blockIdx.x, t = threadIdx.x;
    float y0 = g_fc[t * DD + d];
    float y1 = g_fc[(t + 256) * DD + d];
    float s = y0 + y1;
    float q = fmaf(y0, y0, y1 * y1);
    s = warp_red(s); q = warp_red(q);
    if ((t & 31) == 0) { sms[t >> 5] = s; smq[t >> 5] = q; }
    __syncthreads();
    if (t == 0) {
        float S = 0, Q = 0;
        for (int i = 0; i < 8; i++) { S += sms[i]; Q += smq[i]; }
        float mean = S * (1.0f / 512.0f);
        float var  = Q * (1.0f / 512.0f) - mean * mean;
        float a = g2[d] * rsqrtf(var + EPSBN);
        par[0] = a; par[1] = b2[d] - mean * a;
    }
    __syncthreads();
    float a = par[0], c = par[1];
    float v0 = fmaf(y0, a, c); v0 = v0 > 0.0f ? v0 : 0.01f * v0;
    float v1 = fmaf(y1, a, c); v1 = v1 > 0.0f ? v1 : 0.01f * v1;
    g_xb[t * KPAD + d]         = __float2bfloat16_rn(v0);
    g_xb[(t + 256) * KPAD + d] = __float2bfloat16_rn(v1);
}

// ------------------------------------------------- scores: E loaded once, loop 4 X tiles
// grid 782 entity tiles. A (mma row) = X batch tile, B (col) = E tile. MUFU softplus.
__global__ __launch_bounds__(256, 2)
void k_scores(const float* __restrict__ ew, const float* __restrict__ bias,
              const int* __restrict__ pos) {
    extern __shared__ char smem[];
    uint32_t xs = smem_u32(smem);            // X tile: 128 x 216 bf16 = 55296B
    uint32_t es = xs + 55296;                // E tile: 128 x 216 bf16 = 55296B
    __shared__ float bsh[128];
    __shared__ int   sposm[BATCH];
    __shared__ float red[3][8];
    int t = threadIdx.x, lane = t & 31, wid = t >> 5;
    int NB = blockIdx.x * 128;

    // E tile: fp32 -> bf16 rows (stride 432B), loaded ONCE
    char* esm = smem + 55296;
    for (int idx = t; idx < 6400; idx += 256) {
        int row = idx / 50, q = idx % 50;
        int e = NB + row;
        if (e < NENT) {
            float4 v = *(const float4*)&ew[(size_t)e * DD + q * 4];
            uint32_t u0 = ((uint32_t)__bfloat16_as_ushort(__float2bfloat16_rn(v.y)) << 16)
                        |  (uint32_t)__bfloat16_as_ushort(__float2bfloat16_rn(v.x));
            uint32_t u1 = ((uint32_t)__bfloat16_as_ushort(__float2bfloat16_rn(v.w)) << 16)
                        |  (uint32_t)__bfloat16_as_ushort(__float2bfloat16_rn(v.z));
            *(uint2*)(esm + row * 432 + q * 8) = make_uint2(u0, u1);
        }
    }
    for (int idx = t; idx < 512; idx += 256) {      // zero pad k 200..207
        int row = idx >> 2, c = idx & 3;
        *(uint32_t*)(esm + row * 432 + 400 + c * 4) = 0u;
    }
    if (t < 128) {
        int e = NB + t;
        bsh[t] = (e < NENT) ? bias[e] : 0.0f;
    }
    sposm[t] = pos[t];
    sposm[t + 256] = pos[t + 256];

    int mw = wid >> 2, nw = wid & 3;
    int m_base = mw * 64, n_base = nw * 32;
    uint32_t aaddr[4], baddr[2];
#pragma unroll
    for (int mt = 0; mt < 4; mt++)
        aaddr[mt] = xs + (uint32_t)(m_base + mt * 16 + (lane & 15)) * 432 + (lane >> 4) * 16;
#pragma unroll
    for (int p = 0; p < 2; p++)
        baddr[p] = es + (uint32_t)(n_base + p * 16 + (lane >> 4) * 8 + (lane & 7)) * 432
                      + ((lane >> 3) & 1) * 16;

    float spx = 0.0f, ssx = 0.0f, psx = 0.0f;

    for (int r = 0; r < 4; r++) {
        // copy pre-swizzled X batch tile r
        {
            const uint4* src = (const uint4*)(g_xb + r * 128 * KPAD);
            uint4* dst = (uint4*)smem;
            for (int i = t; i < 3456; i += 256) dst[i] = src[i];
        }
        __syncthreads();

        float acc[4][4][4];
#pragma unroll
        for (int i = 0; i < 4; i++)
#pragma unroll
            for (int j = 0; j < 4; j++)
#pragma unroll
                for (int k = 0; k < 4; k++) acc[i][j][k] = 0.0f;

        for (int ks = 0; ks < 13; ks++) {
            uint32_t A[4][4], Bf[2][4];
#pragma unroll
            for (int mt = 0; mt < 4; mt++) ldm4(A[mt], aaddr[mt] + ks * 32);
#pragma unroll
            for (int p = 0; p < 2; p++)   ldm4(Bf[p], baddr[p] + ks * 32);
#pragma unroll
            for (int mt = 0; mt < 4; mt++)
#pragma unroll
                for (int nt = 0; nt < 4; nt++)
                    mma16816(acc[mt][nt], A[mt], &Bf[nt >> 1][(nt & 1) * 2]);
        }
        __syncthreads();   // all reads of X done before next copy

        // epilogue for this batch tile
#pragma unroll
        for (int mt = 0; mt < 4; mt++) {
            int mrow = r * 128 + m_base + mt * 16 + (lane >> 2);
            int pm0 = sposm[mrow];
            int pm1 = sposm[mrow + 8];
#pragma unroll
            for (int nt = 0; nt < 4; nt++) {
#pragma unroll
                for (int c2 = 0; c2 < 2; c2++) {
                    int n = n_base + nt * 8 + (lane & 3) * 2 + c2;
                    int e = NB + n;
                    if (e < NENT) {
                        float bv = bsh[n];
                        float s0 = acc[mt][nt][c2]     + bv;
                        float s1 = acc[mt][nt][2 + c2] + bv;
                        spx += softplus_fast(s0) + softplus_fast(s1);
                        ssx += s0 + s1;
                        if (pm0 == e) psx += s0;
                        if (pm1 == e) psx += s1;
                    }
                }
            }
        }
    }

    spx = warp_red(spx); ssx = warp_red(ssx); psx = warp_red(psx);
    if (lane == 0) { red[0][wid] = spx; red[1][wid] = ssx; red[2][wid] = psx; }
    __syncthreads();
    if (t == 0) {
        float SP = 0, SS = 0, PS = 0;
        for (int i = 0; i < 8; i++) { SP += red[0][i]; SS += red[1][i]; PS += red[2][i]; }
        atomicAdd(&g_loss[0], (double)SP);
        atomicAdd(&g_loss[1], (double)SS);
        atomicAdd(&g_loss[2], (double)PS);
    }
}

// ------------------------------------------------- final combine
__global__ void k_final(float* out) {
    double sp = g_loss[0], ss = g_loss[1], ps = g_loss[2];
    double kg = (sp - ss / (double)NENT - 0.9 * ps) / ((double)BATCH * (double)NENT);
    double l2 = g_l2[0] / (2.0 * 512.0 * 200.0)
              + g_l2[1] / (2.0 * 512.0 * 200.0)
              + g_l2[2] / (2.0 * 288.0)
              + g_l2[3] / (2.0 * 200.0);
    out[0] = (float)(kg + 1e-5 * l2);
}

extern "C" void kernel_launch(void* const* d_in, const int* in_sizes, int n_in,
                              void* d_out, int out_size) {
    const float* ew   = (const float*)d_in[0];
    const float* rw   = (const float*)d_in[1];
    const float* cw   = (const float*)d_in[2];
    const float* fcw  = (const float*)d_in[4];
    const float* bias = (const float*)d_in[6];
    const float* g0   = (const float*)d_in[7];
    const float* g1   = (const float*)d_in[9];
    const float* b1   = (const float*)d_in[10];
    const float* g2   = (const float*)d_in[11];
    const float* b2   = (const float*)d_in[12];
    const int*   h    = (const int*)d_in[13];
    const int*   r    = (const int*)d_in[14];
    const int*   pos  = (const int*)d_in[15];

    const int SMEM_SC = 2 * 55296;
    cudaFuncSetAttribute(k_scores, cudaFuncAttributeMaxDynamicSharedMemorySize, SMEM_SC);

    k_init<<<200, 256>>>();
    k_l2w<<<256, 256>>>(fcw, cw);
    k_conv<<<128, 352>>>(ew, rw, h, r, cw, g0);
    k_bn1stats<<<dim3(32, 8), 256>>>();
    k_bn1fin<<<1, 32>>>(g1, b1);
    k_fc<<<dim3(4, 2, 9), 256>>>();
    k_bn2<<<200, 256>>>(g2, b2);
    k_scores<<<782, 256, SMEM_SC>>>(ew, bias, pos);
    k_final<<<1, 1>>>((float*)d_out);
}

// round 5
// speedup vs baseline: 2.7666x; 1.1722x over previous
#include <cuda_runtime.h>
#include <cuda_bf16.h>
#include <cstdint>

#define NENT  100000
#define BATCH 512
#define DD    200
#define FCIN  10368
#define NCH   32
#define EPSBN 1e-5f
#define KPAD  216            // padded K stride for X image (432B rows)

// g_conv is CHANNEL-MAJOR: element (b, c, p) at [(c*512 + b)*324 + p]
__device__ float          g_conv[(size_t)BATCH * FCIN];
__device__ float          g_fc[BATCH * DD];
__device__ __nv_bfloat16  g_xb[BATCH * KPAD];          // padded bf16 X image
__device__ __nv_bfloat16  g_fcb[208 * FCIN];           // bf16 fc_w, d-padded
__device__ float          g_a1[NCH];
__device__ float          g_b1[NCH];
__device__ double         g_bn1sum[NCH];
__device__ double         g_bn1sq[NCH];
__device__ double         g_l2[4];
__device__ double         g_loss[3];

// ---------------------------------------------------------------- helpers
__device__ __forceinline__ uint32_t smem_u32(const void* p) {
    uint32_t a;
    asm("{ .reg .u64 t; cvta.to.shared.u64 t, %1; cvt.u32.u64 %0, t; }" : "=r"(a) : "l"(p));
    return a;
}
__device__ __forceinline__ void ldm4(uint32_t* r, uint32_t addr) {
    asm volatile("ldmatrix.sync.aligned.m8n8.x4.shared.b16 {%0,%1,%2,%3}, [%4];"
        : "=r"(r[0]), "=r"(r[1]), "=r"(r[2]), "=r"(r[3]) : "r"(addr));
}
__device__ __forceinline__ void mma16816(float* c, const uint32_t* a, const uint32_t* b) {
    asm volatile("mma.sync.aligned.m16n8k16.row.col.f32.bf16.bf16.f32 "
        "{%0,%1,%2,%3}, {%4,%5,%6,%7}, {%8,%9}, {%0,%1,%2,%3};"
        : "+f"(c[0]), "+f"(c[1]), "+f"(c[2]), "+f"(c[3])
        : "r"(a[0]), "r"(a[1]), "r"(a[2]), "r"(a[3]), "r"(b[0]), "r"(b[1]));
}
__device__ __forceinline__ float warp_red(float v) {
#pragma unroll
    for (int o = 16; o > 0; o >>= 1) v += __shfl_down_sync(0xffffffffu, v, o);
    return v;
}
// MUFU softplus: max(s,0) + ln2*lg2(1 + 2^(-|s|*log2e))
__device__ __forceinline__ float softplus_fast(float s) {
    float e, l;
    float xn = -fabsf(s) * 1.4426950408889634f;
    asm("ex2.approx.f32 %0, %1;" : "=f"(e) : "f"(xn));
    float arg = 1.0f + e;
    asm("lg2.approx.f32 %0, %1;" : "=f"(l) : "f"(arg));
    return fmaxf(s, 0.0f) + 0.69314718055994531f * l;
}

// ---------------------------------------------------------------- init
__global__ void k_init() {
    int idx = blockIdx.x * blockDim.x + threadIdx.x;
    int stride = gridDim.x * blockDim.x;
    for (int i = idx; i < BATCH * DD; i += stride) g_fc[i] = 0.0f;
    uint32_t* xb = (uint32_t*)g_xb;
    for (int i = idx; i < BATCH * KPAD / 2; i += stride) xb[i] = 0u;
    uint32_t* fp = (uint32_t*)(g_fcb + 200 * FCIN);
    for (int i = idx; i < 8 * FCIN / 2; i += stride) fp[i] = 0u;
    if (idx < NCH) { g_bn1sum[idx] = 0.0; g_bn1sq[idx] = 0.0; }
    if (idx < 4)   g_l2[idx]  = 0.0;
    if (idx < 3)   g_loss[idx] = 0.0;
}

// ------------------------------------------------- fcw L2 + bf16 convert; conv_w L2
__global__ void k_l2w(const float* __restrict__ fcw, const float* __restrict__ cw) {
    __shared__ float sm[8];
    int t = threadIdx.x;
    float loc = 0.0f;
    for (int i = blockIdx.x * blockDim.x + t; i < DD * FCIN; i += gridDim.x * blockDim.x) {
        float v = fcw[i];
        loc = fmaf(v, v, loc);
        g_fcb[i] = __float2bfloat16_rn(v);
    }
    loc = warp_red(loc);
    if ((t & 31) == 0) sm[t >> 5] = loc;
    __syncthreads();
    if (t == 0) {
        float S = 0; for (int i = 0; i < 8; i++) S += sm[i];
        atomicAdd(&g_l2[3], (double)S);
    }
    if (blockIdx.x == 0) {
        __syncthreads();
        float lc = 0.0f;
        if (t < NCH * 9) { float v = cw[t]; lc = v * v; }
        lc = warp_red(lc);
        if ((t & 31) == 0) sm[t >> 5] = lc;
        __syncthreads();
        if (t == 0) {
            float S = 0; for (int i = 0; i < 8; i++) S += sm[i];
            atomicAdd(&g_l2[2], (double)S);
        }
    }
}

// ------------------------------------------------- fused gather + emb L2 + conv
__global__ void k_conv(const float* __restrict__ ew, const float* __restrict__ rw,
                       const int* __restrict__ h, const int* __restrict__ r,
                       const float* __restrict__ cw, const float* __restrict__ g0p) {
    __shared__ float xn[4][400];
    __shared__ float wts[NCH * 9];
    __shared__ float shh[11], shr[11];
    int b0 = blockIdx.x * 4, t = threadIdx.x;
    float g0 = g0p[0];
    float l2h = 0.0f, l2r = 0.0f;
    for (int i = t; i < 1600; i += 352) {
        int bb = i / 400, pos = i % 400, b = b0 + bb;
        float v;
        if (pos < 200) { v = ew[(size_t)h[b] * DD + pos]; l2h = fmaf(v, v, l2h); }
        else           { v = rw[(size_t)r[b] * DD + (pos - 200)]; l2r = fmaf(v, v, l2r); }
        xn[bb][pos] = g0 * v;
    }
    if (t < NCH * 9) wts[t] = cw[t];
    l2h = warp_red(l2h); l2r = warp_red(l2r);
    if ((t & 31) == 0) { shh[t >> 5] = l2h; shr[t >> 5] = l2r; }
    __syncthreads();
    if (t == 0) {
        float H = 0, R = 0;
        for (int i = 0; i < 11; i++) { H += shh[i]; R += shr[i]; }
        atomicAdd(&g_l2[0], (double)H);
        atomicAdd(&g_l2[1], (double)R);
    }
    if (t < 324) {
        int i = t / 18, j = t % 18;
        int boff = i * 20 + j;
        for (int c = 0; c < NCH; c++) {
#pragma unroll
            for (int bb = 0; bb < 4; bb++) {
                const float* base = &xn[bb][boff];
                float acc = 0.0f;
#pragma unroll
                for (int ki = 0; ki < 3; ki++)
#pragma unroll
                    for (int kj = 0; kj < 3; kj++)
                        acc = fmaf(base[ki * 20 + kj], wts[c * 9 + ki * 3 + kj], acc);
                g_conv[((size_t)c * 512 + b0 + bb) * 324 + t] = acc;
            }
        }
    }
}

// ------------------------------------------------- bn1 stats: coalesced channel-major stream
// channel c occupies a contiguous 512*324 = 165888-float (41472 float4) span.
__global__ void k_bn1stats() {
    __shared__ float sms[8], smq[8];
    int c = blockIdx.x, sl = blockIdx.y, t = threadIdx.x;
    const float4* p = (const float4*)&g_conv[(size_t)c * 512 * 324];
    float s = 0.0f, q = 0.0f;
    int end = (sl + 1) * 5184;
    for (int i = sl * 5184 + t; i < end; i += 256) {
        float4 v = p[i];
        s += (v.x + v.y) + (v.z + v.w);
        q = fmaf(v.x, v.x, q); q = fmaf(v.y, v.y, q);
        q = fmaf(v.z, v.z, q); q = fmaf(v.w, v.w, q);
    }
    s = warp_red(s); q = warp_red(q);
    if ((t & 31) == 0) { sms[t >> 5] = s; smq[t >> 5] = q; }
    __syncthreads();
    if (t == 0) {
        float S = 0, Q = 0;
        for (int i = 0; i < 8; i++) { S += sms[i]; Q += smq[i]; }
        atomicAdd(&g_bn1sum[c], (double)S);
        atomicAdd(&g_bn1sq[c],  (double)Q);
    }
}

// ------------------------------------------------- bn1 finalize
__global__ void k_bn1fin(const float* __restrict__ g1, const float* __restrict__ b1) {
    int t = threadIdx.x;
    if (t < NCH) {
        double cnt = 512.0 * 324.0;
        double mean = g_bn1sum[t] / cnt;
        double var  = g_bn1sq[t] / cnt - mean * mean;
        float a = g1[t] * rsqrtf((float)var + EPSBN);
        g_a1[t] = a;
        g_b1[t] = b1[t] - (float)mean * a;
    }
}

// ------------------------------------------------- FC via bf16 mma: g_fc += relu(bn1(conv)) @ fcw^T
__global__ __launch_bounds__(256, 2) void k_fc() {
    __shared__ __align__(16) char As[128 * 144];
    __shared__ __align__(16) char Bs[128 * 144];
    __shared__ float a_tab[64], b_tab[64];
    uint32_t as_ = smem_u32(As), bs_ = smem_u32(Bs);
    int t = threadIdx.x, lane = t & 31, wid = t >> 5;
    int m0 = blockIdx.x * 128, n0 = blockIdx.y * 128;
    int kseg = blockIdx.z * 1152;

    int mw = wid >> 2, nw = wid & 3;
    int m_base = mw * 64, n_base = nw * 32;
    uint32_t aaddr[4], baddr[2];
#pragma unroll
    for (int mt = 0; mt < 4; mt++)
        aaddr[mt] = as_ + (uint32_t)(m_base + mt * 16 + (lane & 15)) * 144 + (lane >> 4) * 16;
#pragma unroll
    for (int p = 0; p < 2; p++)
        baddr[p] = bs_ + (uint32_t)(n_base + p * 16 + (lane >> 4) * 8 + (lane & 7)) * 144
                       + ((lane >> 3) & 1) * 16;

    float acc[4][4][4];
#pragma unroll
    for (int i = 0; i < 4; i++)
#pragma unroll
        for (int j = 0; j < 4; j++)
#pragma unroll
            for (int k = 0; k < 4; k++) acc[i][j][k] = 0.0f;

    for (int ch = 0; ch < 18; ch++) {
        int kb = kseg + ch * 64;
        if (t < 64) {
            int c = (kb + t) / 324;
            a_tab[t] = g_a1[c];
            b_tab[t] = g_b1[c];
        }
        __syncthreads();
        // A: 128 rows x 64 k, channel-major gather, affine+relu, cvt bf16
        {
            int row = t >> 1, half = t & 1;
#pragma unroll
            for (int j = 0; j < 8; j++) {
                int kc = half * 32 + j * 4;
                int k4 = kb + kc;
                int c = k4 / 324, pp = k4 - c * 324;
                float4 v = *(const float4*)&g_conv[((size_t)c * 512 + m0 + row) * 324 + pp];
                float y0 = fmaxf(fmaf(v.x, a_tab[kc],     b_tab[kc]),     0.0f);
                float y1 = fmaxf(fmaf(v.y, a_tab[kc + 1], b_tab[kc + 1]), 0.0f);
                float y2 = fmaxf(fmaf(v.z, a_tab[kc + 2], b_tab[kc + 2]), 0.0f);
                float y3 = fmaxf(fmaf(v.w, a_tab[kc + 3], b_tab[kc + 3]), 0.0f);
                uint32_t u0 = ((uint32_t)__bfloat16_as_ushort(__float2bfloat16_rn(y1)) << 16)
                            |  (uint32_t)__bfloat16_as_ushort(__float2bfloat16_rn(y0));
                uint32_t u1 = ((uint32_t)__bfloat16_as_ushort(__float2bfloat16_rn(y3)) << 16)
                            |  (uint32_t)__bfloat16_as_ushort(__float2bfloat16_rn(y2));
                *(uint2*)&As[row * 144 + kc * 2] = make_uint2(u0, u1);
            }
        }
        // B: 128 rows (d) x 64 k from pre-converted g_fcb
        {
#pragma unroll
            for (int j = 0; j < 2; j++) {
                int id = t + j * 256;
                int row = id >> 2, off = (id & 3) * 16;
                int d = n0 + row;
                uint4 v0 = make_uint4(0, 0, 0, 0), v1 = make_uint4(0, 0, 0, 0);
                if (d < 208) {
                    const uint4* src = (const uint4*)&g_fcb[(size_t)d * FCIN + kb + off];
                    v0 = src[0]; v1 = src[1];
                }
                uint4* dst = (uint4*)&Bs[row * 144 + off * 2];
                dst[0] = v0; dst[1] = v1;
            }
        }
        __syncthreads();
#pragma unroll
        for (int ks = 0; ks < 4; ks++) {
            uint32_t A[4][4], Bf[2][4];
#pragma unroll
            for (int mt = 0; mt < 4; mt++) ldm4(A[mt], aaddr[mt] + ks * 32);
#pragma unroll
            for (int p = 0; p < 2; p++)   ldm4(Bf[p], baddr[p] + ks * 32);
#pragma unroll
            for (int mt = 0; mt < 4; mt++)
#pragma unroll
                for (int nt = 0; nt < 4; nt++)
                    mma16816(acc[mt][nt], A[mt], &Bf[nt >> 1][(nt & 1) * 2]);
        }
        __syncthreads();
    }
#pragma unroll
    for (int mt = 0; mt < 4; mt++) {
        int r0 = m0 + m_base + mt * 16 + (lane >> 2);
#pragma unroll
        for (int nt = 0; nt < 4; nt++) {
#pragma unroll
            for (int c2 = 0; c2 < 2; c2++) {
                int d = n0 + n_base + nt * 8 + (lane & 3) * 2 + c2;
                if (d < DD) {
                    atomicAdd(&g_fc[r0 * DD + d],       acc[mt][nt][c2]);
                    atomicAdd(&g_fc[(r0 + 8) * DD + d], acc[mt][nt][2 + c2]);
                }
            }
        }
    }
}

// ------------------------------------------------- bn2 + leaky relu -> padded bf16 X image
__global__ void k_bn2(const float* __restrict__ g2, const float* __restrict__ b2) {
    __shared__ float sms[8], smq[8], par[2];
    int d = blockIdx.x, t = threadIdx.x;
    float y0 = g_fc[t * DD + d];
    float y1 = g_fc[(t + 256) * DD + d];
    float s = y0 + y1;
    float q = fmaf(y0, y0, y1 * y1);
    s = warp_red(s); q = warp_red(q);
    if ((t & 31) == 0) { sms[t >> 5] = s; smq[t >> 5] = q; }
    __syncthreads();
    if (t == 0) {
        float S = 0, Q = 0;
        for (int i = 0; i < 8; i++) { S += sms[i]; Q += smq[i]; }
        float mean = S * (1.0f / 512.0f);
        float var  = Q * (1.0f / 512.0f) - mean * mean;
        float a = g2[d] * rsqrtf(var + EPSBN);
        par[0] = a; par[1] = b2[d] - mean * a;
    }
    __syncthreads();
    float a = par[0], c = par[1];
    float v0 = fmaf(y0, a, c); v0 = v0 > 0.0f ? v0 : 0.01f * v0;
    float v1 = fmaf(y1, a, c); v1 = v1 > 0.0f ? v1 : 0.01f * v1;
    g_xb[t * KPAD + d]         = __float2bfloat16_rn(v0);
    g_xb[(t + 256) * KPAD + d] = __float2bfloat16_rn(v1);
}

// ------------------------------------------------- scores: E loaded once, loop 4 X tiles
__global__ __launch_bounds__(256, 2)
void k_scores(const float* __restrict__ ew, const float* __restrict__ bias,
              const int* __restrict__ pos) {
    extern __shared__ char smem[];
    uint32_t xs = smem_u32(smem);            // X tile: 128 x 216 bf16 = 55296B
    uint32_t es = xs + 55296;                // E tile: 128 x 216 bf16 = 55296B
    __shared__ float bsh[128];
    __shared__ int   sposm[BATCH];
    __shared__ float red[3][8];
    int t = threadIdx.x, lane = t & 31, wid = t >> 5;
    int NB = blockIdx.x * 128;

    char* esm = smem + 55296;
    for (int idx = t; idx < 6400; idx += 256) {
        int row = idx / 50, q = idx % 50;
        int e = NB + row;
        if (e < NENT) {
            float4 v = *(const float4*)&ew[(size_t)e * DD + q * 4];
            uint32_t u0 = ((uint32_t)__bfloat16_as_ushort(__float2bfloat16_rn(v.y)) << 16)
                        |  (uint32_t)__bfloat16_as_ushort(__float2bfloat16_rn(v.x));
            uint32_t u1 = ((uint32_t)__bfloat16_as_ushort(__float2bfloat16_rn(v.w)) << 16)
                        |  (uint32_t)__bfloat16_as_ushort(__float2bfloat16_rn(v.z));
            *(uint2*)(esm + row * 432 + q * 8) = make_uint2(u0, u1);
        }
    }
    for (int idx = t; idx < 512; idx += 256) {
        int row = idx >> 2, c = idx & 3;
        *(uint32_t*)(esm + row * 432 + 400 + c * 4) = 0u;
    }
    if (t < 128) {
        int e = NB + t;
        bsh[t] = (e < NENT) ? bias[e] : 0.0f;
    }
    sposm[t] = pos[t];
    sposm[t + 256] = pos[t + 256];

    int mw = wid >> 2, nw = wid & 3;
    int m_base = mw * 64, n_base = nw * 32;
    uint32_t aaddr[4], baddr[2];
#pragma unroll
    for (int mt = 0; mt < 4; mt++)
        aaddr[mt] = xs + (uint32_t)(m_base + mt * 16 + (lane & 15)) * 432 + (lane >> 4) * 16;
#pragma unroll
    for (int p = 0; p < 2; p++)
        baddr[p] = es + (uint32_t)(n_base + p * 16 + (lane >> 4) * 8 + (lane & 7)) * 432
                      + ((lane >> 3) & 1) * 16;

    float spx = 0.0f, ssx = 0.0f, psx = 0.0f;

    for (int r = 0; r < 4; r++) {
        {
            const uint4* src = (const uint4*)(g_xb + r * 128 * KPAD);
            uint4* dst = (uint4*)smem;
            for (int i = t; i < 3456; i += 256) dst[i] = src[i];
        }
        __syncthreads();

        float acc[4][4][4];
#pragma unroll
        for (int i = 0; i < 4; i++)
#pragma unroll
            for (int j = 0; j < 4; j++)
#pragma unroll
                for (int k = 0; k < 4; k++) acc[i][j][k] = 0.0f;

        for (int ks = 0; ks < 13; ks++) {
            uint32_t A[4][4], Bf[2][4];
#pragma unroll
            for (int mt = 0; mt < 4; mt++) ldm4(A[mt], aaddr[mt] + ks * 32);
#pragma unroll
            for (int p = 0; p < 2; p++)   ldm4(Bf[p], baddr[p] + ks * 32);
#pragma unroll
            for (int mt = 0; mt < 4; mt++)
#pragma unroll
                for (int nt = 0; nt < 4; nt++)
                    mma16816(acc[mt][nt], A[mt], &Bf[nt >> 1][(nt & 1) * 2]);
        }
        __syncthreads();

#pragma unroll
        for (int mt = 0; mt < 4; mt++) {
            int mrow = r * 128 + m_base + mt * 16 + (lane >> 2);
            int pm0 = sposm[mrow];
            int pm1 = sposm[mrow + 8];
#pragma unroll
            for (int nt = 0; nt < 4; nt++) {
#pragma unroll
                for (int c2 = 0; c2 < 2; c2++) {
                    int n = n_base + nt * 8 + (lane & 3) * 2 + c2;
                    int e = NB + n;
                    if (e < NENT) {
                        float bv = bsh[n];
                        float s0 = acc[mt][nt][c2]     + bv;
                        float s1 = acc[mt][nt][2 + c2] + bv;
                        spx += softplus_fast(s0) + softplus_fast(s1);
                        ssx += s0 + s1;
                        if (pm0 == e) psx += s0;
                        if (pm1 == e) psx += s1;
                    }
                }
            }
        }
    }

    spx = warp_red(spx); ssx = warp_red(ssx); psx = warp_red(psx);
    if (lane == 0) { red[0][wid] = spx; red[1][wid] = ssx; red[2][wid] = psx; }
    __syncthreads();
    if (t == 0) {
        float SP = 0, SS = 0, PS = 0;
        for (int i = 0; i < 8; i++) { SP += red[0][i]; SS += red[1][i]; PS += red[2][i]; }
        atomicAdd(&g_loss[0], (double)SP);
        atomicAdd(&g_loss[1], (double)SS);
        atomicAdd(&g_loss[2], (double)PS);
    }
}

// ------------------------------------------------- final combine
__global__ void k_final(float* out) {
    double sp = g_loss[0], ss = g_loss[1], ps = g_loss[2];
    double kg = (sp - ss / (double)NENT - 0.9 * ps) / ((double)BATCH * (double)NENT);
    double l2 = g_l2[0] / (2.0 * 512.0 * 200.0)
              + g_l2[1] / (2.0 * 512.0 * 200.0)
              + g_l2[2] / (2.0 * 288.0)
              + g_l2[3] / (2.0 * 200.0);
    out[0] = (float)(kg + 1e-5 * l2);
}

extern "C" void kernel_launch(void* const* d_in, const int* in_sizes, int n_in,
                              void* d_out, int out_size) {
    const float* ew   = (const float*)d_in[0];
    const float* rw   = (const float*)d_in[1];
    const float* cw   = (const float*)d_in[2];
    const float* fcw  = (const float*)d_in[4];
    const float* bias = (const float*)d_in[6];
    const float* g0   = (const float*)d_in[7];
    const float* g1   = (const float*)d_in[9];
    const float* b1   = (const float*)d_in[10];
    const float* g2   = (const float*)d_in[11];
    const float* b2   = (const float*)d_in[12];
    const int*   h    = (const int*)d_in[13];
    const int*   r    = (const int*)d_in[14];
    const int*   pos  = (const int*)d_in[15];

    const int SMEM_SC = 2 * 55296;
    cudaFuncSetAttribute(k_scores, cudaFuncAttributeMaxDynamicSharedMemorySize, SMEM_SC);

    k_init<<<200, 256>>>();
    k_l2w<<<256, 256>>>(fcw, cw);
    k_conv<<<128, 352>>>(ew, rw, h, r, cw, g0);
    k_bn1stats<<<dim3(32, 8), 256>>>();
    k_bn1fin<<<1, 32>>>(g1, b1);
    k_fc<<<dim3(4, 2, 9), 256>>>();
    k_bn2<<<200, 256>>>(g2, b2);
    k_scores<<<782, 256, SMEM_SC>>>(ew, bias, pos);
    k_final<<<1, 1>>>((float*)d_out);
}

// round 6
// speedup vs baseline: 3.0381x; 1.0981x over previous
#include <cuda_runtime.h>
#include <cuda_bf16.h>
#include <cstdint>

#define NENT  100000
#define BATCH 512
#define DD    200
#define FCIN  10368
#define NCH   32
#define EPSBN 1e-5f
#define KPAD  216            // padded K stride for X image (432B rows)

// g_conv is CHANNEL-MAJOR: element (b, c, p) at [(c*512 + b)*324 + p]
__device__ float          g_conv[(size_t)BATCH * FCIN];
__device__ float          g_fc[BATCH * DD];
__device__ __nv_bfloat16  g_xb[BATCH * KPAD];          // padded bf16 X image
__device__ __nv_bfloat16  g_fcb[208 * FCIN];           // bf16 fc_w, d-padded
__device__ float          g_a1[NCH];
__device__ float          g_b1[NCH];
__device__ double         g_bn1sum[NCH];
__device__ double         g_bn1sq[NCH];
__device__ double         g_l2[4];
__device__ double         g_loss[3];

// ---------------------------------------------------------------- helpers
__device__ __forceinline__ uint32_t smem_u32(const void* p) {
    uint32_t a;
    asm("{ .reg .u64 t; cvta.to.shared.u64 t, %1; cvt.u32.u64 %0, t; }" : "=r"(a) : "l"(p));
    return a;
}
__device__ __forceinline__ void ldm4(uint32_t* r, uint32_t addr) {
    asm volatile("ldmatrix.sync.aligned.m8n8.x4.shared.b16 {%0,%1,%2,%3}, [%4];"
        : "=r"(r[0]), "=r"(r[1]), "=r"(r[2]), "=r"(r[3]) : "r"(addr));
}
__device__ __forceinline__ void mma16816(float* c, const uint32_t* a, const uint32_t* b) {
    asm volatile("mma.sync.aligned.m16n8k16.row.col.f32.bf16.bf16.f32 "
        "{%0,%1,%2,%3}, {%4,%5,%6,%7}, {%8,%9}, {%0,%1,%2,%3};"
        : "+f"(c[0]), "+f"(c[1]), "+f"(c[2]), "+f"(c[3])
        : "r"(a[0]), "r"(a[1]), "r"(a[2]), "r"(a[3]), "r"(b[0]), "r"(b[1]));
}
#define CP_ASYNC16(dst, src) \
    asm volatile("cp.async.cg.shared.global [%0], [%1], 16;" :: "r"(dst), "l"(src))
#define CP_COMMIT() asm volatile("cp.async.commit_group;" ::: "memory")
#define CP_WAIT0()  asm volatile("cp.async.wait_group 0;" ::: "memory")

__device__ __forceinline__ float warp_red(float v) {
#pragma unroll
    for (int o = 16; o > 0; o >>= 1) v += __shfl_down_sync(0xffffffffu, v, o);
    return v;
}
// MUFU softplus: max(s,0) + ln2*lg2(1 + 2^(-|s|*log2e))
__device__ __forceinline__ float softplus_fast(float s) {
    float e, l;
    float xn = -fabsf(s) * 1.4426950408889634f;
    asm("ex2.approx.f32 %0, %1;" : "=f"(e) : "f"(xn));
    float arg = 1.0f + e;
    asm("lg2.approx.f32 %0, %1;" : "=f"(l) : "f"(arg));
    return fmaxf(s, 0.0f) + 0.69314718055994531f * l;
}

// ---------------------------------------------------------------- init
__global__ void k_init() {
    int idx = blockIdx.x * blockDim.x + threadIdx.x;
    int stride = gridDim.x * blockDim.x;
    for (int i = idx; i < BATCH * DD; i += stride) g_fc[i] = 0.0f;
    uint32_t* xb = (uint32_t*)g_xb;
    for (int i = idx; i < BATCH * KPAD / 2; i += stride) xb[i] = 0u;
    uint32_t* fp = (uint32_t*)(g_fcb + 200 * FCIN);
    for (int i = idx; i < 8 * FCIN / 2; i += stride) fp[i] = 0u;
    if (idx < NCH) { g_bn1sum[idx] = 0.0; g_bn1sq[idx] = 0.0; }
    if (idx < 4)   g_l2[idx]  = 0.0;
    if (idx < 3)   g_loss[idx] = 0.0;
}

// ------------------------------------------------- fcw L2 + bf16 convert; conv_w L2
__global__ void k_l2w(const float* __restrict__ fcw, const float* __restrict__ cw) {
    __shared__ float sm[8];
    int t = threadIdx.x;
    float loc = 0.0f;
    for (int i = blockIdx.x * blockDim.x + t; i < DD * FCIN; i += gridDim.x * blockDim.x) {
        float v = fcw[i];
        loc = fmaf(v, v, loc);
        g_fcb[i] = __float2bfloat16_rn(v);
    }
    loc = warp_red(loc);
    if ((t & 31) == 0) sm[t >> 5] = loc;
    __syncthreads();
    if (t == 0) {
        float S = 0; for (int i = 0; i < 8; i++) S += sm[i];
        atomicAdd(&g_l2[3], (double)S);
    }
    if (blockIdx.x == 0) {
        __syncthreads();
        float lc = 0.0f;
        if (t < NCH * 9) { float v = cw[t]; lc = v * v; }
        lc = warp_red(lc);
        if ((t & 31) == 0) sm[t >> 5] = lc;
        __syncthreads();
        if (t == 0) {
            float S = 0; for (int i = 0; i < 8; i++) S += sm[i];
            atomicAdd(&g_l2[2], (double)S);
        }
    }
}

// ------------------------------------------------- fused gather + emb L2 + conv
// grid (128, 2): x = 4-batch group, y = 16-channel half.
__global__ void k_conv(const float* __restrict__ ew, const float* __restrict__ rw,
                       const int* __restrict__ h, const int* __restrict__ r,
                       const float* __restrict__ cw, const float* __restrict__ g0p) {
    __shared__ float xn[4][400];
    __shared__ float wts[NCH * 9];
    __shared__ float shh[11], shr[11];
    int b0 = blockIdx.x * 4, t = threadIdx.x;
    int c0 = blockIdx.y * 16;
    float g0 = g0p[0];
    float l2h = 0.0f, l2r = 0.0f;
    for (int i = t; i < 1600; i += 352) {
        int bb = i / 400, pos = i % 400, b = b0 + bb;
        float v;
        if (pos < 200) { v = ew[(size_t)h[b] * DD + pos]; l2h = fmaf(v, v, l2h); }
        else           { v = rw[(size_t)r[b] * DD + (pos - 200)]; l2r = fmaf(v, v, l2r); }
        xn[bb][pos] = g0 * v;
    }
    if (t < NCH * 9) wts[t] = cw[t];
    if (blockIdx.y == 0) {
        l2h = warp_red(l2h); l2r = warp_red(l2r);
        if ((t & 31) == 0) { shh[t >> 5] = l2h; shr[t >> 5] = l2r; }
    }
    __syncthreads();
    if (blockIdx.y == 0 && t == 0) {
        float H = 0, R = 0;
        for (int i = 0; i < 11; i++) { H += shh[i]; R += shr[i]; }
        atomicAdd(&g_l2[0], (double)H);
        atomicAdd(&g_l2[1], (double)R);
    }
    if (t < 324) {
        int i = t / 18, j = t % 18;
        int boff = i * 20 + j;
        for (int c = c0; c < c0 + 16; c++) {
#pragma unroll
            for (int bb = 0; bb < 4; bb++) {
                const float* base = &xn[bb][boff];
                float acc = 0.0f;
#pragma unroll
                for (int ki = 0; ki < 3; ki++)
#pragma unroll
                    for (int kj = 0; kj < 3; kj++)
                        acc = fmaf(base[ki * 20 + kj], wts[c * 9 + ki * 3 + kj], acc);
                g_conv[((size_t)c * 512 + b0 + bb) * 324 + t] = acc;
            }
        }
    }
}

// ------------------------------------------------- bn1 stats: coalesced channel-major stream
__global__ void k_bn1stats() {
    __shared__ float sms[8], smq[8];
    int c = blockIdx.x, sl = blockIdx.y, t = threadIdx.x;
    const float4* p = (const float4*)&g_conv[(size_t)c * 512 * 324];
    float s = 0.0f, q = 0.0f;
    int end = (sl + 1) * 5184;
    for (int i = sl * 5184 + t; i < end; i += 256) {
        float4 v = p[i];
        s += (v.x + v.y) + (v.z + v.w);
        q = fmaf(v.x, v.x, q); q = fmaf(v.y, v.y, q);
        q = fmaf(v.z, v.z, q); q = fmaf(v.w, v.w, q);
    }
    s = warp_red(s); q = warp_red(q);
    if ((t & 31) == 0) { sms[t >> 5] = s; smq[t >> 5] = q; }
    __syncthreads();
    if (t == 0) {
        float S = 0, Q = 0;
        for (int i = 0; i < 8; i++) { S += sms[i]; Q += smq[i]; }
        atomicAdd(&g_bn1sum[c], (double)S);
        atomicAdd(&g_bn1sq[c],  (double)Q);
    }
}

// ------------------------------------------------- bn1 finalize
__global__ void k_bn1fin(const float* __restrict__ g1, const float* __restrict__ b1) {
    int t = threadIdx.x;
    if (t < NCH) {
        double cnt = 512.0 * 324.0;
        double mean = g_bn1sum[t] / cnt;
        double var  = g_bn1sq[t] / cnt - mean * mean;
        float a = g1[t] * rsqrtf((float)var + EPSBN);
        g_a1[t] = a;
        g_b1[t] = b1[t] - (float)mean * a;
    }
}

// ------------------------------------------------- FC via bf16 mma (144 CTAs)
__global__ __launch_bounds__(256, 2) void k_fc() {
    __shared__ __align__(16) char As[128 * 144];
    __shared__ __align__(16) char Bs[128 * 144];
    __shared__ float a_tab[64], b_tab[64];
    uint32_t as_ = smem_u32(As), bs_ = smem_u32(Bs);
    int t = threadIdx.x, lane = t & 31, wid = t >> 5;
    int m0 = blockIdx.x * 128, n0 = blockIdx.y * 128;
    int kseg = blockIdx.z * 576;

    int mw = wid >> 2, nw = wid & 3;
    int m_base = mw * 64, n_base = nw * 32;
    uint32_t aaddr[4], baddr[2];
#pragma unroll
    for (int mt = 0; mt < 4; mt++)
        aaddr[mt] = as_ + (uint32_t)(m_base + mt * 16 + (lane & 15)) * 144 + (lane >> 4) * 16;
#pragma unroll
    for (int p = 0; p < 2; p++)
        baddr[p] = bs_ + (uint32_t)(n_base + p * 16 + (lane >> 4) * 8 + (lane & 7)) * 144
                       + ((lane >> 3) & 1) * 16;

    float acc[4][4][4];
#pragma unroll
    for (int i = 0; i < 4; i++)
#pragma unroll
        for (int j = 0; j < 4; j++)
#pragma unroll
            for (int k = 0; k < 4; k++) acc[i][j][k] = 0.0f;

    for (int ch = 0; ch < 9; ch++) {
        int kb = kseg + ch * 64;
        if (t < 64) {
            int c = (kb + t) / 324;
            a_tab[t] = g_a1[c];
            b_tab[t] = g_b1[c];
        }
        __syncthreads();
        // A: 128 rows x 64 k, channel-major gather, affine+relu, cvt bf16
        {
            int row = t >> 1, half = t & 1;
#pragma unroll
            for (int j = 0; j < 8; j++) {
                int kc = half * 32 + j * 4;
                int k4 = kb + kc;
                int c = k4 / 324, pp = k4 - c * 324;
                float4 v = *(const float4*)&g_conv[((size_t)c * 512 + m0 + row) * 324 + pp];
                float y0 = fmaxf(fmaf(v.x, a_tab[kc],     b_tab[kc]),     0.0f);
                float y1 = fmaxf(fmaf(v.y, a_tab[kc + 1], b_tab[kc + 1]), 0.0f);
                float y2 = fmaxf(fmaf(v.z, a_tab[kc + 2], b_tab[kc + 2]), 0.0f);
                float y3 = fmaxf(fmaf(v.w, a_tab[kc + 3], b_tab[kc + 3]), 0.0f);
                uint32_t u0 = ((uint32_t)__bfloat16_as_ushort(__float2bfloat16_rn(y1)) << 16)
                            |  (uint32_t)__bfloat16_as_ushort(__float2bfloat16_rn(y0));
                uint32_t u1 = ((uint32_t)__bfloat16_as_ushort(__float2bfloat16_rn(y3)) << 16)
                            |  (uint32_t)__bfloat16_as_ushort(__float2bfloat16_rn(y2));
                *(uint2*)&As[row * 144 + kc * 2] = make_uint2(u0, u1);
            }
        }
        // B: 128 rows (d) x 64 k from pre-converted g_fcb
        {
#pragma unroll
            for (int j = 0; j < 2; j++) {
                int id = t + j * 256;
                int row = id >> 2, off = (id & 3) * 16;
                int d = n0 + row;
                uint4 v0 = make_uint4(0, 0, 0, 0), v1 = make_uint4(0, 0, 0, 0);
                if (d < 208) {
                    const uint4* src = (const uint4*)&g_fcb[(size_t)d * FCIN + kb + off];
                    v0 = src[0]; v1 = src[1];
                }
                uint4* dst = (uint4*)&Bs[row * 144 + off * 2];
                dst[0] = v0; dst[1] = v1;
            }
        }
        __syncthreads();
#pragma unroll
        for (int ks = 0; ks < 4; ks++) {
            uint32_t A[4][4], Bf[2][4];
#pragma unroll
            for (int mt = 0; mt < 4; mt++) ldm4(A[mt], aaddr[mt] + ks * 32);
#pragma unroll
            for (int p = 0; p < 2; p++)   ldm4(Bf[p], baddr[p] + ks * 32);
#pragma unroll
            for (int mt = 0; mt < 4; mt++)
#pragma unroll
                for (int nt = 0; nt < 4; nt++)
                    mma16816(acc[mt][nt], A[mt], &Bf[nt >> 1][(nt & 1) * 2]);
        }
        __syncthreads();
    }
#pragma unroll
    for (int mt = 0; mt < 4; mt++) {
        int r0 = m0 + m_base + mt * 16 + (lane >> 2);
#pragma unroll
        for (int nt = 0; nt < 4; nt++) {
#pragma unroll
            for (int c2 = 0; c2 < 2; c2++) {
                int d = n0 + n_base + nt * 8 + (lane & 3) * 2 + c2;
                if (d < DD) {
                    atomicAdd(&g_fc[r0 * DD + d],       acc[mt][nt][c2]);
                    atomicAdd(&g_fc[(r0 + 8) * DD + d], acc[mt][nt][2 + c2]);
                }
            }
        }
    }
}

// ------------------------------------------------- bn2 + leaky relu -> padded bf16 X image
__global__ void k_bn2(const float* __restrict__ g2, const float* __restrict__ b2) {
    __shared__ float sms[8], smq[8], par[2];
    int d = blockIdx.x, t = threadIdx.x;
    float y0 = g_fc[t * DD + d];
    float y1 = g_fc[(t + 256) * DD + d];
    float s = y0 + y1;
    float q = fmaf(y0, y0, y1 * y1);
    s = warp_red(s); q = warp_red(q);
    if ((t & 31) == 0) { sms[t >> 5] = s; smq[t >> 5] = q; }
    __syncthreads();
    if (t == 0) {
        float S = 0, Q = 0;
        for (int i = 0; i < 8; i++) { S += sms[i]; Q += smq[i]; }
        float mean = S * (1.0f / 512.0f);
        float var  = Q * (1.0f / 512.0f) - mean * mean;
        float a = g2[d] * rsqrtf(var + EPSBN);
        par[0] = a; par[1] = b2[d] - mean * a;
    }
    __syncthreads();
    float a = par[0], c = par[1];
    float v0 = fmaf(y0, a, c); v0 = v0 > 0.0f ? v0 : 0.01f * v0;
    float v1 = fmaf(y1, a, c); v1 = v1 > 0.0f ? v1 : 0.01f * v1;
    g_xb[t * KPAD + d]         = __float2bfloat16_rn(v0);
    g_xb[(t + 256) * KPAD + d] = __float2bfloat16_rn(v1);
}

// ------------------------------------------------- positive-target scores (512 dots)
__global__ void k_psx(const float* __restrict__ ew, const float* __restrict__ bias,
                      const int* __restrict__ pos) {
    __shared__ double acc8[8];
    int b = blockIdx.x * 8 + (threadIdx.x >> 5);
    int lane = threadIdx.x & 31;
    int p = pos[b];
    const float* e = ew + (size_t)p * DD;
    float s = 0.0f;
    for (int d = lane; d < DD; d += 32)
        s = fmaf(__bfloat162float(g_xb[b * KPAD + d]), e[d], s);
    s = warp_red(s);
    if (lane == 0) acc8[threadIdx.x >> 5] = (double)(s + bias[p]);
    __syncthreads();
    if (threadIdx.x == 0) {
        double S = 0;
        for (int i = 0; i < 8; i++) S += acc8[i];
        atomicAdd(&g_loss[2], S);
    }
}

// ------------------------------------------------- scores: E once, cp.async X pipeline
__global__ __launch_bounds__(256, 2)
void k_scores(const float* __restrict__ ew, const float* __restrict__ bias) {
    extern __shared__ char smem[];
    uint32_t xs = smem_u32(smem);            // X tile: 128 x 216 bf16 = 55296B
    uint32_t es = xs + 55296;                // E tile: 128 x 216 bf16 = 55296B
    __shared__ float bsh[128];
    __shared__ float red[2][8];
    int t = threadIdx.x, lane = t & 31, wid = t >> 5;
    int NB = blockIdx.x * 128;

    // prefetch X tile 0 while E is loaded/converted
    {
        const char* src = (const char*)g_xb;
        for (int i = t; i < 3456; i += 256) CP_ASYNC16(xs + i * 16, src + i * 16);
        CP_COMMIT();
    }
    char* esm = smem + 55296;
    for (int idx = t; idx < 6400; idx += 256) {
        int row = idx / 50, q = idx % 50;
        int e = NB + row;
        if (e < NENT) {
            float4 v = *(const float4*)&ew[(size_t)e * DD + q * 4];
            uint32_t u0 = ((uint32_t)__bfloat16_as_ushort(__float2bfloat16_rn(v.y)) << 16)
                        |  (uint32_t)__bfloat16_as_ushort(__float2bfloat16_rn(v.x));
            uint32_t u1 = ((uint32_t)__bfloat16_as_ushort(__float2bfloat16_rn(v.w)) << 16)
                        |  (uint32_t)__bfloat16_as_ushort(__float2bfloat16_rn(v.z));
            *(uint2*)(esm + row * 432 + q * 8) = make_uint2(u0, u1);
        }
    }
    for (int idx = t; idx < 512; idx += 256) {
        int row = idx >> 2, c = idx & 3;
        *(uint32_t*)(esm + row * 432 + 400 + c * 4) = 0u;
    }
    if (t < 128) {
        int e = NB + t;
        bsh[t] = (e < NENT) ? bias[e] : 0.0f;
    }
    CP_WAIT0();
    __syncthreads();

    int mw = wid >> 2, nw = wid & 3;
    int m_base = mw * 64, n_base = nw * 32;
    uint32_t aaddr[4], baddr[2];
#pragma unroll
    for (int mt = 0; mt < 4; mt++)
        aaddr[mt] = xs + (uint32_t)(m_base + mt * 16 + (lane & 15)) * 432 + (lane >> 4) * 16;
#pragma unroll
    for (int p = 0; p < 2; p++)
        baddr[p] = es + (uint32_t)(n_base + p * 16 + (lane >> 4) * 8 + (lane & 7)) * 432
                      + ((lane >> 3) & 1) * 16;

    float spx = 0.0f, ssx = 0.0f;

    for (int r = 0; r < 4; r++) {
        float acc[4][4][4];
#pragma unroll
        for (int i = 0; i < 4; i++)
#pragma unroll
            for (int j = 0; j < 4; j++)
#pragma unroll
                for (int k = 0; k < 4; k++) acc[i][j][k] = 0.0f;

        for (int ks = 0; ks < 13; ks++) {
            uint32_t A[4][4], Bf[2][4];
#pragma unroll
            for (int mt = 0; mt < 4; mt++) ldm4(A[mt], aaddr[mt] + ks * 32);
#pragma unroll
            for (int p = 0; p < 2; p++)   ldm4(Bf[p], baddr[p] + ks * 32);
#pragma unroll
            for (int mt = 0; mt < 4; mt++)
#pragma unroll
                for (int nt = 0; nt < 4; nt++)
                    mma16816(acc[mt][nt], A[mt], &Bf[nt >> 1][(nt & 1) * 2]);
        }
        __syncthreads();             // all warps done reading X tile r

        // overlap: prefetch next X tile during epilogue
        if (r < 3) {
            const char* src = (const char*)(g_xb + (r + 1) * 128 * KPAD);
            for (int i = t; i < 3456; i += 256) CP_ASYNC16(xs + i * 16, src + i * 16);
            CP_COMMIT();
        }

        // epilogue: bias + softplus + sums (no target compares — k_psx owns those)
#pragma unroll
        for (int mt = 0; mt < 4; mt++) {
#pragma unroll
            for (int nt = 0; nt < 4; nt++) {
#pragma unroll
                for (int c2 = 0; c2 < 2; c2++) {
                    int n = n_base + nt * 8 + (lane & 3) * 2 + c2;
                    if (NB + n < NENT) {
                        float bv = bsh[n];
                        float s0 = acc[mt][nt][c2]     + bv;
                        float s1 = acc[mt][nt][2 + c2] + bv;
                        spx += softplus_fast(s0) + softplus_fast(s1);
                        ssx += s0 + s1;
                    }
                }
            }
        }
        if (r < 3) { CP_WAIT0(); __syncthreads(); }
    }

    spx = warp_red(spx); ssx = warp_red(ssx);
    if (lane == 0) { red[0][wid] = spx; red[1][wid] = ssx; }
    __syncthreads();
    if (t == 0) {
        float SP = 0, SS = 0;
        for (int i = 0; i < 8; i++) { SP += red[0][i]; SS += red[1][i]; }
        atomicAdd(&g_loss[0], (double)SP);
        atomicAdd(&g_loss[1], (double)SS);
    }
}

// ------------------------------------------------- final combine
__global__ void k_final(float* out) {
    double sp = g_loss[0], ss = g_loss[1], ps = g_loss[2];
    double kg = (sp - ss / (double)NENT - 0.9 * ps) / ((double)BATCH * (double)NENT);
    double l2 = g_l2[0] / (2.0 * 512.0 * 200.0)
              + g_l2[1] / (2.0 * 512.0 * 200.0)
              + g_l2[2] / (2.0 * 288.0)
              + g_l2[3] / (2.0 * 200.0);
    out[0] = (float)(kg + 1e-5 * l2);
}

extern "C" void kernel_launch(void* const* d_in, const int* in_sizes, int n_in,
                              void* d_out, int out_size) {
    const float* ew   = (const float*)d_in[0];
    const float* rw   = (const float*)d_in[1];
    const float* cw   = (const float*)d_in[2];
    const float* fcw  = (const float*)d_in[4];
    const float* bias = (const float*)d_in[6];
    const float* g0   = (const float*)d_in[7];
    const float* g1   = (const float*)d_in[9];
    const float* b1   = (const float*)d_in[10];
    const float* g2   = (const float*)d_in[11];
    const float* b2   = (const float*)d_in[12];
    const int*   h    = (const int*)d_in[13];
    const int*   r    = (const int*)d_in[14];
    const int*   pos  = (const int*)d_in[15];

    const int SMEM_SC = 2 * 55296;
    cudaFuncSetAttribute(k_scores, cudaFuncAttributeMaxDynamicSharedMemorySize, SMEM_SC);

    k_init<<<200, 256>>>();
    k_l2w<<<256, 256>>>(fcw, cw);
    k_conv<<<dim3(128, 2), 352>>>(ew, rw, h, r, cw, g0);
    k_bn1stats<<<dim3(32, 8), 256>>>();
    k_bn1fin<<<1, 32>>>(g1, b1);
    k_fc<<<dim3(4, 2, 18), 256>>>();
    k_bn2<<<200, 256>>>(g2, b2);
    k_psx<<<64, 256>>>(ew, bias, pos);
    k_scores<<<782, 256, SMEM_SC>>>(ew, bias);
    k_final<<<1, 1>>>((float*)d_out);
}

// round 7
// speedup vs baseline: 3.1555x; 1.0386x over previous
#include <cuda_runtime.h>
#include <cuda_bf16.h>
#include <cstdint>

#define NENT  100000
#define BATCH 512
#define DD    200
#define FCIN  10368
#define NCH   32
#define EPSBN 1e-5f
#define KPAD  216            // padded K stride for X image (432B rows)

// g_conv is CHANNEL-MAJOR: element (b, c, p) at [(c*512 + b)*324 + p]
__device__ float          g_conv[(size_t)BATCH * FCIN];
__device__ float          g_fc[BATCH * DD];
__device__ __nv_bfloat16  g_xb[BATCH * KPAD];          // padded bf16 X image
__device__ __nv_bfloat16  g_fcb[(size_t)256 * FCIN];   // bf16 fc_w (rows >=200 unused)
__device__ float          g_a1[NCH];
__device__ float          g_b1[NCH];
__device__ double         g_bn1sum[NCH];
__device__ double         g_bn1sq[NCH];
__device__ double         g_l2[4];
__device__ double         g_loss[3];

// ---------------------------------------------------------------- helpers
__device__ __forceinline__ uint32_t smem_u32(const void* p) {
    uint32_t a;
    asm("{ .reg .u64 t; cvta.to.shared.u64 t, %1; cvt.u32.u64 %0, t; }" : "=r"(a) : "l"(p));
    return a;
}
__device__ __forceinline__ void ldm4(uint32_t* r, uint32_t addr) {
    asm volatile("ldmatrix.sync.aligned.m8n8.x4.shared.b16 {%0,%1,%2,%3}, [%4];"
        : "=r"(r[0]), "=r"(r[1]), "=r"(r[2]), "=r"(r[3]) : "r"(addr));
}
__device__ __forceinline__ void mma16816(float* c, const uint32_t* a, const uint32_t* b) {
    asm volatile("mma.sync.aligned.m16n8k16.row.col.f32.bf16.bf16.f32 "
        "{%0,%1,%2,%3}, {%4,%5,%6,%7}, {%8,%9}, {%0,%1,%2,%3};"
        : "+f"(c[0]), "+f"(c[1]), "+f"(c[2]), "+f"(c[3])
        : "r"(a[0]), "r"(a[1]), "r"(a[2]), "r"(a[3]), "r"(b[0]), "r"(b[1]));
}
#define CP_ASYNC16(dst, src) \
    asm volatile("cp.async.cg.shared.global [%0], [%1], 16;" :: "r"(dst), "l"(src))
#define CP_COMMIT() asm volatile("cp.async.commit_group;" ::: "memory")
#define CP_WAIT0()  asm volatile("cp.async.wait_group 0;" ::: "memory")

__device__ __forceinline__ float warp_red(float v) {
#pragma unroll
    for (int o = 16; o > 0; o >>= 1) v += __shfl_down_sync(0xffffffffu, v, o);
    return v;
}
// MUFU softplus: max(s,0) + ln2*lg2(1 + 2^(-|s|*log2e))  (2 MUFU)
__device__ __forceinline__ float softplus_fast(float s) {
    float e, l;
    float xn = -fabsf(s) * 1.4426950408889634f;
    asm("ex2.approx.f32 %0, %1;" : "=f"(e) : "f"(xn));
    float arg = 1.0f + e;
    asm("lg2.approx.f32 %0, %1;" : "=f"(l) : "f"(arg));
    return fmaxf(s, 0.0f) + 0.69314718055994531f * l;
}
// FMA-exp2 softplus: exp via magic-round + deg-5 Taylor, then 1 MUFU lg2
__device__ __forceinline__ float softplus_fma(float s) {
    float y = fminf(fabsf(s), 80.0f) * -1.4426950408889634f;
    float z = y + 12582912.0f;
    int   e = __float_as_int(z) - 0x4B400000;
    float f = y - (z - 12582912.0f);
    float u = f * 0.69314718055994531f;
    float p = fmaf(u, 8.33333333e-3f, 4.16666667e-2f);
    p = fmaf(p, u, 1.66666667e-1f);
    p = fmaf(p, u, 0.5f);
    p = fmaf(p, u, 1.0f);
    p = fmaf(p, u, 1.0f);
    float tt = p * __int_as_float((e + 127) << 23);
    float l;
    asm("lg2.approx.f32 %0, %1;" : "=f"(l) : "f"(1.0f + tt));
    return fmaxf(s, 0.0f) + 0.69314718055994531f * l;
}

// ---------------------------------------------------------------- init
__global__ void k_init() {
    int idx = blockIdx.x * blockDim.x + threadIdx.x;
    int stride = gridDim.x * blockDim.x;
    for (int i = idx; i < BATCH * DD; i += stride) g_fc[i] = 0.0f;
    uint32_t* xb = (uint32_t*)g_xb;
    for (int i = idx; i < BATCH * KPAD / 2; i += stride) xb[i] = 0u;
    if (idx < NCH) { g_bn1sum[idx] = 0.0; g_bn1sq[idx] = 0.0; }
    if (idx < 4)   g_l2[idx]  = 0.0;
    if (idx < 3)   g_loss[idx] = 0.0;
}

// ------------------------------------------------- fcw L2 + bf16 convert; conv_w L2
__global__ void k_l2w(const float* __restrict__ fcw, const float* __restrict__ cw) {
    __shared__ float sm[8];
    int t = threadIdx.x;
    float loc = 0.0f;
    for (int i = blockIdx.x * blockDim.x + t; i < DD * FCIN; i += gridDim.x * blockDim.x) {
        float v = fcw[i];
        loc = fmaf(v, v, loc);
        g_fcb[i] = __float2bfloat16_rn(v);
    }
    loc = warp_red(loc);
    if ((t & 31) == 0) sm[t >> 5] = loc;
    __syncthreads();
    if (t == 0) {
        float S = 0; for (int i = 0; i < 8; i++) S += sm[i];
        atomicAdd(&g_l2[3], (double)S);
    }
    if (blockIdx.x == 0) {
        __syncthreads();
        float lc = 0.0f;
        if (t < NCH * 9) { float v = cw[t]; lc = v * v; }
        lc = warp_red(lc);
        if ((t & 31) == 0) sm[t >> 5] = lc;
        __syncthreads();
        if (t == 0) {
            float S = 0; for (int i = 0; i < 8; i++) S += sm[i];
            atomicAdd(&g_l2[2], (double)S);
        }
    }
}

// ------------------------------------------------- fused gather + emb L2 + conv
__global__ void k_conv(const float* __restrict__ ew, const float* __restrict__ rw,
                       const int* __restrict__ h, const int* __restrict__ r,
                       const float* __restrict__ cw, const float* __restrict__ g0p) {
    __shared__ float xn[4][400];
    __shared__ float wts[NCH * 9];
    __shared__ float shh[11], shr[11];
    int b0 = blockIdx.x * 4, t = threadIdx.x;
    int c0 = blockIdx.y * 16;
    float g0 = g0p[0];
    float l2h = 0.0f, l2r = 0.0f;
    for (int i = t; i < 1600; i += 352) {
        int bb = i / 400, pos = i % 400, b = b0 + bb;
        float v;
        if (pos < 200) { v = ew[(size_t)h[b] * DD + pos]; l2h = fmaf(v, v, l2h); }
        else           { v = rw[(size_t)r[b] * DD + (pos - 200)]; l2r = fmaf(v, v, l2r); }
        xn[bb][pos] = g0 * v;
    }
    if (t < NCH * 9) wts[t] = cw[t];
    if (blockIdx.y == 0) {
        l2h = warp_red(l2h); l2r = warp_red(l2r);
        if ((t & 31) == 0) { shh[t >> 5] = l2h; shr[t >> 5] = l2r; }
    }
    __syncthreads();
    if (blockIdx.y == 0 && t == 0) {
        float H = 0, R = 0;
        for (int i = 0; i < 11; i++) { H += shh[i]; R += shr[i]; }
        atomicAdd(&g_l2[0], (double)H);
        atomicAdd(&g_l2[1], (double)R);
    }
    if (t < 324) {
        int i = t / 18, j = t % 18;
        int boff = i * 20 + j;
        for (int c = c0; c < c0 + 16; c++) {
#pragma unroll
            for (int bb = 0; bb < 4; bb++) {
                const float* base = &xn[bb][boff];
                float acc = 0.0f;
#pragma unroll
                for (int ki = 0; ki < 3; ki++)
#pragma unroll
                    for (int kj = 0; kj < 3; kj++)
                        acc = fmaf(base[ki * 20 + kj], wts[c * 9 + ki * 3 + kj], acc);
                g_conv[((size_t)c * 512 + b0 + bb) * 324 + t] = acc;
            }
        }
    }
}

// ------------------------------------------------- bn1 stats: coalesced channel-major stream
__global__ void k_bn1stats() {
    __shared__ float sms[8], smq[8];
    int c = blockIdx.x, sl = blockIdx.y, t = threadIdx.x;
    const float4* p = (const float4*)&g_conv[(size_t)c * 512 * 324];
    float s = 0.0f, q = 0.0f;
    int end = (sl + 1) * 2592;
    for (int i = sl * 2592 + t; i < end; i += 256) {
        float4 v = p[i];
        s += (v.x + v.y) + (v.z + v.w);
        q = fmaf(v.x, v.x, q); q = fmaf(v.y, v.y, q);
        q = fmaf(v.z, v.z, q); q = fmaf(v.w, v.w, q);
    }
    s = warp_red(s); q = warp_red(q);
    if ((t & 31) == 0) { sms[t >> 5] = s; smq[t >> 5] = q; }
    __syncthreads();
    if (t == 0) {
        float S = 0, Q = 0;
        for (int i = 0; i < 8; i++) { S += sms[i]; Q += smq[i]; }
        atomicAdd(&g_bn1sum[c], (double)S);
        atomicAdd(&g_bn1sq[c],  (double)Q);
    }
}

// ------------------------------------------------- bn1 finalize
__global__ void k_bn1fin(const float* __restrict__ g1, const float* __restrict__ b1) {
    int t = threadIdx.x;
    if (t < NCH) {
        double cnt = 512.0 * 324.0;
        double mean = g_bn1sum[t] / cnt;
        double var  = g_bn1sq[t] / cnt - mean * mean;
        float a = g1[t] * rsqrtf((float)var + EPSBN);
        g_a1[t] = a;
        g_b1[t] = b1[t] - (float)mean * a;
    }
}

// ------------------------------------------------- FC via bf16 mma, cp.async pipeline
// smem buffers: [A0][A1][B0][B1] each 128x144B. One __syncthreads per chunk.
__global__ __launch_bounds__(256, 2) void k_fc() {
    __shared__ __align__(16) char AB[4][128 * 144];
    __shared__ float a_tab[576], b_tab[576];
    uint32_t as0 = smem_u32(AB[0]);
    uint32_t bs0 = as0 + 2 * 18432;
    int t = threadIdx.x, lane = t & 31, wid = t >> 5;
    int m0 = blockIdx.x * 128, n0 = blockIdx.y * 128;
    int kseg = blockIdx.z * 576;

    for (int i = t; i < 576; i += 256) {
        int c = (kseg + i) / 324;
        a_tab[i] = g_a1[c];
        b_tab[i] = g_b1[c];
    }
    // prefetch B chunk 0 into B0
    {
#pragma unroll
        for (int j = 0; j < 4; j++) {
            int u = t + j * 256;
            int row = u >> 3, off = u & 7;
            CP_ASYNC16(bs0 + row * 144 + off * 16,
                       (const char*)&g_fcb[(size_t)(n0 + row) * FCIN + kseg + off * 8]);
        }
        CP_COMMIT();
    }
    __syncthreads();   // tabs visible

    int mw = wid >> 2, nw = wid & 3;
    int m_base = mw * 64, n_base = nw * 32;
    uint32_t aaddr[4], baddr[2];
#pragma unroll
    for (int mt = 0; mt < 4; mt++)
        aaddr[mt] = as0 + (uint32_t)(m_base + mt * 16 + (lane & 15)) * 144 + (lane >> 4) * 16;
#pragma unroll
    for (int p = 0; p < 2; p++)
        baddr[p] = bs0 + (uint32_t)(n_base + p * 16 + (lane >> 4) * 8 + (lane & 7)) * 144
                       + ((lane >> 3) & 1) * 16;

    float acc[4][4][4];
#pragma unroll
    for (int i = 0; i < 4; i++)
#pragma unroll
        for (int j = 0; j < 4; j++)
#pragma unroll
            for (int k = 0; k < 4; k++) acc[i][j][k] = 0.0f;

    for (int ch = 0; ch < 9; ch++) {
        int buf = ch & 1;
        int kb = kseg + ch * 64;
        // pack A chunk into A[buf] (safe: last reads of A[buf] were fenced at iter ch-1 sync)
        {
            int row = t >> 1, half = t & 1;
            char* As = AB[buf];
#pragma unroll
            for (int j = 0; j < 8; j++) {
                int kc = half * 32 + j * 4;
                int kti = ch * 64 + kc;
                int k4 = kb + kc;
                int c = k4 / 324, pp = k4 - c * 324;
                float4 v = *(const float4*)&g_conv[((size_t)c * 512 + m0 + row) * 324 + pp];
                float y0 = fmaxf(fmaf(v.x, a_tab[kti],     b_tab[kti]),     0.0f);
                float y1 = fmaxf(fmaf(v.y, a_tab[kti + 1], b_tab[kti + 1]), 0.0f);
                float y2 = fmaxf(fmaf(v.z, a_tab[kti + 2], b_tab[kti + 2]), 0.0f);
                float y3 = fmaxf(fmaf(v.w, a_tab[kti + 3], b_tab[kti + 3]), 0.0f);
                uint32_t u0 = ((uint32_t)__bfloat16_as_ushort(__float2bfloat16_rn(y1)) << 16)
                            |  (uint32_t)__bfloat16_as_ushort(__float2bfloat16_rn(y0));
                uint32_t u1 = ((uint32_t)__bfloat16_as_ushort(__float2bfloat16_rn(y3)) << 16)
                            |  (uint32_t)__bfloat16_as_ushort(__float2bfloat16_rn(y2));
                *(uint2*)&As[row * 144 + kc * 2] = make_uint2(u0, u1);
            }
        }
        CP_WAIT0();          // B[buf] landed
        __syncthreads();     // A[buf]+B[buf] visible; all prior reads of B[buf^1] done
        if (ch < 8) {        // issue B for next chunk into B[buf^1] (overlaps mma below)
            int kb2 = kb + 64;
#pragma unroll
            for (int j = 0; j < 4; j++) {
                int u = t + j * 256;
                int row = u >> 3, off = u & 7;
                CP_ASYNC16(bs0 + (1 - buf) * 18432 + row * 144 + off * 16,
                           (const char*)&g_fcb[(size_t)(n0 + row) * FCIN + kb2 + off * 8]);
            }
            CP_COMMIT();
        }
        uint32_t ao = buf * 18432, bo = buf * 18432;
#pragma unroll
        for (int ks = 0; ks < 4; ks++) {
            uint32_t A[4][4], Bf[2][4];
#pragma unroll
            for (int mt = 0; mt < 4; mt++) ldm4(A[mt], aaddr[mt] + ao + ks * 32);
#pragma unroll
            for (int p = 0; p < 2; p++)   ldm4(Bf[p], baddr[p] + bo + ks * 32);
#pragma unroll
            for (int mt = 0; mt < 4; mt++)
#pragma unroll
                for (int nt = 0; nt < 4; nt++)
                    mma16816(acc[mt][nt], A[mt], &Bf[nt >> 1][(nt & 1) * 2]);
        }
    }
#pragma unroll
    for (int mt = 0; mt < 4; mt++) {
        int r0 = m0 + m_base + mt * 16 + (lane >> 2);
#pragma unroll
        for (int nt = 0; nt < 4; nt++) {
#pragma unroll
            for (int c2 = 0; c2 < 2; c2++) {
                int d = n0 + n_base + nt * 8 + (lane & 3) * 2 + c2;
                if (d < DD) {
                    atomicAdd(&g_fc[r0 * DD + d],       acc[mt][nt][c2]);
                    atomicAdd(&g_fc[(r0 + 8) * DD + d], acc[mt][nt][2 + c2]);
                }
            }
        }
    }
}

// ------------------------------------------------- bn2 + leaky relu -> padded bf16 X image
__global__ void k_bn2(const float* __restrict__ g2, const float* __restrict__ b2) {
    __shared__ float sms[8], smq[8], par[2];
    int d = blockIdx.x, t = threadIdx.x;
    float y0 = g_fc[t * DD + d];
    float y1 = g_fc[(t + 256) * DD + d];
    float s = y0 + y1;
    float q = fmaf(y0, y0, y1 * y1);
    s = warp_red(s); q = warp_red(q);
    if ((t & 31) == 0) { sms[t >> 5] = s; smq[t >> 5] = q; }
    __syncthreads();
    if (t == 0) {
        float S = 0, Q = 0;
        for (int i = 0; i < 8; i++) { S += sms[i]; Q += smq[i]; }
        float mean = S * (1.0f / 512.0f);
        float var  = Q * (1.0f / 512.0f) - mean * mean;
        float a = g2[d] * rsqrtf(var + EPSBN);
        par[0] = a; par[1] = b2[d] - mean * a;
    }
    __syncthreads();
    float a = par[0], c = par[1];
    float v0 = fmaf(y0, a, c); v0 = v0 > 0.0f ? v0 : 0.01f * v0;
    float v1 = fmaf(y1, a, c); v1 = v1 > 0.0f ? v1 : 0.01f * v1;
    g_xb[t * KPAD + d]         = __float2bfloat16_rn(v0);
    g_xb[(t + 256) * KPAD + d] = __float2bfloat16_rn(v1);
}

// ------------------------------------------------- positive-target scores (512 dots)
__global__ void k_psx(const float* __restrict__ ew, const float* __restrict__ bias,
                      const int* __restrict__ pos) {
    __shared__ double acc8[8];
    int b = blockIdx.x * 8 + (threadIdx.x >> 5);
    int lane = threadIdx.x & 31;
    int p = pos[b];
    const float* e = ew + (size_t)p * DD;
    float s = 0.0f;
    for (int d = lane; d < DD; d += 32)
        s = fmaf(__bfloat162float(g_xb[b * KPAD + d]), e[d], s);
    s = warp_red(s);
    if (lane == 0) acc8[threadIdx.x >> 5] = (double)(s + bias[p]);
    __syncthreads();
    if (threadIdx.x == 0) {
        double S = 0;
        for (int i = 0; i < 8; i++) S += acc8[i];
        atomicAdd(&g_loss[2], S);
    }
}

// ------------------------------------------------- scores: E once, cp.async X pipeline
__global__ __launch_bounds__(256, 2)
void k_scores(const float* __restrict__ ew, const float* __restrict__ bias) {
    extern __shared__ char smem[];
    uint32_t xs = smem_u32(smem);            // X tile: 128 x 216 bf16 = 55296B
    uint32_t es = xs + 55296;                // E tile: 128 x 216 bf16 = 55296B
    __shared__ float bsh[128];
    __shared__ float red[2][8];
    int t = threadIdx.x, lane = t & 31, wid = t >> 5;
    int NB = blockIdx.x * 128;

    // prefetch X tile 0 while E is loaded/converted
    {
        const char* src = (const char*)g_xb;
        for (int i = t; i < 3456; i += 256) CP_ASYNC16(xs + i * 16, src + i * 16);
        CP_COMMIT();
    }
    char* esm = smem + 55296;
    for (int idx = t; idx < 6400; idx += 256) {
        int row = idx / 50, q = idx % 50;
        int e = NB + row;
        if (e < NENT) {
            float4 v = *(const float4*)&ew[(size_t)e * DD + q * 4];
            uint32_t u0 = ((uint32_t)__bfloat16_as_ushort(__float2bfloat16_rn(v.y)) << 16)
                        |  (uint32_t)__bfloat16_as_ushort(__float2bfloat16_rn(v.x));
            uint32_t u1 = ((uint32_t)__bfloat16_as_ushort(__float2bfloat16_rn(v.w)) << 16)
                        |  (uint32_t)__bfloat16_as_ushort(__float2bfloat16_rn(v.z));
            *(uint2*)(esm + row * 432 + q * 8) = make_uint2(u0, u1);
        }
    }
    for (int idx = t; idx < 512; idx += 256) {
        int row = idx >> 2, c = idx & 3;
        *(uint32_t*)(esm + row * 432 + 400 + c * 4) = 0u;
    }
    if (t < 128) {
        int e = NB + t;
        bsh[t] = (e < NENT) ? bias[e] : 0.0f;
    }
    CP_WAIT0();
    __syncthreads();

    int mw = wid >> 2, nw = wid & 3;
    int m_base = mw * 64, n_base = nw * 32;
    uint32_t aaddr[4], baddr[2];
#pragma unroll
    for (int mt = 0; mt < 4; mt++)
        aaddr[mt] = xs + (uint32_t)(m_base + mt * 16 + (lane & 15)) * 432 + (lane >> 4) * 16;
#pragma unroll
    for (int p = 0; p < 2; p++)
        baddr[p] = es + (uint32_t)(n_base + p * 16 + (lane >> 4) * 8 + (lane & 7)) * 432
                      + ((lane >> 3) & 1) * 16;

    float spx = 0.0f, ssx = 0.0f;

    for (int r = 0; r < 4; r++) {
        float acc[4][4][4];
#pragma unroll
        for (int i = 0; i < 4; i++)
#pragma unroll
            for (int j = 0; j < 4; j++)
#pragma unroll
                for (int k = 0; k < 4; k++) acc[i][j][k] = 0.0f;

        for (int ks = 0; ks < 13; ks++) {
            uint32_t A[4][4], Bf[2][4];
#pragma unroll
            for (int mt = 0; mt < 4; mt++) ldm4(A[mt], aaddr[mt] + ks * 32);
#pragma unroll
            for (int p = 0; p < 2; p++)   ldm4(Bf[p], baddr[p] + ks * 32);
#pragma unroll
            for (int mt = 0; mt < 4; mt++)
#pragma unroll
                for (int nt = 0; nt < 4; nt++)
                    mma16816(acc[mt][nt], A[mt], &Bf[nt >> 1][(nt & 1) * 2]);
        }
        __syncthreads();             // all warps done reading X tile r

        // overlap: prefetch next X tile during epilogue
        if (r < 3) {
            const char* src = (const char*)(g_xb + (r + 1) * 128 * KPAD);
            for (int i = t; i < 3456; i += 256) CP_ASYNC16(xs + i * 16, src + i * 16);
            CP_COMMIT();
        }

        // epilogue: bias + hybrid softplus (balance MUFU/FMA pipes) + score sum
#pragma unroll
        for (int nt = 0; nt < 4; nt++) {
#pragma unroll
            for (int c2 = 0; c2 < 2; c2++) {
                int n = n_base + nt * 8 + (lane & 3) * 2 + c2;
                if (NB + n < NENT) {
                    float bv = bsh[n];
#pragma unroll
                    for (int mt = 0; mt < 4; mt++) {
                        float s0 = acc[mt][nt][c2]     + bv;
                        float s1 = acc[mt][nt][2 + c2] + bv;
                        spx += softplus_fast(s0) + softplus_fma(s1);
                        ssx += s0 + s1;
                    }
                }
            }
        }
        if (r < 3) { CP_WAIT0(); __syncthreads(); }
    }

    spx = warp_red(spx); ssx = warp_red(ssx);
    if (lane == 0) { red[0][wid] = spx; red[1][wid] = ssx; }
    __syncthreads();
    if (t == 0) {
        float SP = 0, SS = 0;
        for (int i = 0; i < 8; i++) { SP += red[0][i]; SS += red[1][i]; }
        atomicAdd(&g_loss[0], (double)SP);
        atomicAdd(&g_loss[1], (double)SS);
    }
}

// ------------------------------------------------- final combine
__global__ void k_final(float* out) {
    double sp = g_loss[0], ss = g_loss[1], ps = g_loss[2];
    double kg = (sp - ss / (double)NENT - 0.9 * ps) / ((double)BATCH * (double)NENT);
    double l2 = g_l2[0] / (2.0 * 512.0 * 200.0)
              + g_l2[1] / (2.0 * 512.0 * 200.0)
              + g_l2[2] / (2.0 * 288.0)
              + g_l2[3] / (2.0 * 200.0);
    out[0] = (float)(kg + 1e-5 * l2);
}

extern "C" void kernel_launch(void* const* d_in, const int* in_sizes, int n_in,
                              void* d_out, int out_size) {
    const float* ew   = (const float*)d_in[0];
    const float* rw   = (const float*)d_in[1];
    const float* cw   = (const float*)d_in[2];
    const float* fcw  = (const float*)d_in[4];
    const float* bias = (const float*)d_in[6];
    const float* g0   = (const float*)d_in[7];
    const float* g1   = (const float*)d_in[9];
    const float* b1   = (const float*)d_in[10];
    const float* g2   = (const float*)d_in[11];
    const float* b2   = (const float*)d_in[12];
    const int*   h    = (const int*)d_in[13];
    const int*   r    = (const int*)d_in[14];
    const int*   pos  = (const int*)d_in[15];

    const int SMEM_SC = 2 * 55296;
    cudaFuncSetAttribute(k_scores, cudaFuncAttributeMaxDynamicSharedMemorySize, SMEM_SC);

    k_init<<<200, 256>>>();
    k_l2w<<<256, 256>>>(fcw, cw);
    k_conv<<<dim3(128, 2), 352>>>(ew, rw, h, r, cw, g0);
    k_bn1stats<<<dim3(32, 16), 256>>>();
    k_bn1fin<<<1, 32>>>(g1, b1);
    k_fc<<<dim3(4, 2, 18), 256>>>();
    k_bn2<<<200, 256>>>(g2, b2);
    k_psx<<<64, 256>>>(ew, bias, pos);
    k_scores<<<782, 256, SMEM_SC>>>(ew, bias);
    k_final<<<1, 1>>>((float*)d_out);
}

// round 8
// speedup vs baseline: 3.7095x; 1.1755x over previous
#include <cuda_runtime.h>
#include <cuda_bf16.h>
#include <cstdint>

#define NENT  100000
#define BATCH 512
#define DD    200
#define FCIN  10368
#define NCH   32
#define EPSBN 1e-5f
#define KPAD  216            // padded K stride for X image (432B rows)

// g_conv is CHANNEL-MAJOR: element (b, c, p) at [(c*512 + b)*324 + p]
__device__ float          g_conv[(size_t)BATCH * FCIN];
__device__ float          g_fc[BATCH * DD];
__device__ __nv_bfloat16  g_xb[BATCH * KPAD];          // padded bf16 X image (col200 = 1.0)
__device__ __nv_bfloat16  g_fcb[(size_t)256 * FCIN];   // bf16 fc_w (rows >=200 unused)
__device__ float          g_a1[NCH];
__device__ float          g_b1[NCH];
__device__ double         g_bn1sum[NCH];
__device__ double         g_bn1sq[NCH];
__device__ double         g_l2[4];
__device__ double         g_loss[3];

// ---------------------------------------------------------------- helpers
__device__ __forceinline__ uint32_t smem_u32(const void* p) {
    uint32_t a;
    asm("{ .reg .u64 t; cvta.to.shared.u64 t, %1; cvt.u32.u64 %0, t; }" : "=r"(a) : "l"(p));
    return a;
}
__device__ __forceinline__ void ldm4(uint32_t* r, uint32_t addr) {
    asm volatile("ldmatrix.sync.aligned.m8n8.x4.shared.b16 {%0,%1,%2,%3}, [%4];"
        : "=r"(r[0]), "=r"(r[1]), "=r"(r[2]), "=r"(r[3]) : "r"(addr));
}
__device__ __forceinline__ void mma16816(float* c, const uint32_t* a, const uint32_t* b) {
    asm volatile("mma.sync.aligned.m16n8k16.row.col.f32.bf16.bf16.f32 "
        "{%0,%1,%2,%3}, {%4,%5,%6,%7}, {%8,%9}, {%0,%1,%2,%3};"
        : "+f"(c[0]), "+f"(c[1]), "+f"(c[2]), "+f"(c[3])
        : "r"(a[0]), "r"(a[1]), "r"(a[2]), "r"(a[3]), "r"(b[0]), "r"(b[1]));
}
#define CP_ASYNC16(dst, src) \
    asm volatile("cp.async.cg.shared.global [%0], [%1], 16;" :: "r"(dst), "l"(src))
#define CP_COMMIT() asm volatile("cp.async.commit_group;" ::: "memory")
#define CP_WAIT0()  asm volatile("cp.async.wait_group 0;" ::: "memory")

__device__ __forceinline__ float warp_red(float v) {
#pragma unroll
    for (int o = 16; o > 0; o >>= 1) v += __shfl_down_sync(0xffffffffu, v, o);
    return v;
}
__device__ __forceinline__ uint32_t bf2pack(float a, float b) {
    return ((uint32_t)__bfloat16_as_ushort(__float2bfloat16_rn(b)) << 16)
         |  (uint32_t)__bfloat16_as_ushort(__float2bfloat16_rn(a));
}
// MUFU softplus: max(s,0) + ln2*lg2(1 + 2^(-|s|*log2e))  (2 MUFU)
__device__ __forceinline__ float softplus_fast(float s) {
    float e, l;
    float xn = -fabsf(s) * 1.4426950408889634f;
    asm("ex2.approx.f32 %0, %1;" : "=f"(e) : "f"(xn));
    float arg = 1.0f + e;
    asm("lg2.approx.f32 %0, %1;" : "=f"(l) : "f"(arg));
    return fmaxf(s, 0.0f) + 0.69314718055994531f * l;
}
// FMA-exp2 softplus: exp via magic-round + deg-5 Taylor, then 1 MUFU lg2
__device__ __forceinline__ float softplus_fma(float s) {
    float y = fminf(fabsf(s), 80.0f) * -1.4426950408889634f;
    float z = y + 12582912.0f;
    int   e = __float_as_int(z) - 0x4B400000;
    float f = y - (z - 12582912.0f);
    float u = f * 0.69314718055994531f;
    float p = fmaf(u, 8.33333333e-3f, 4.16666667e-2f);
    p = fmaf(p, u, 1.66666667e-1f);
    p = fmaf(p, u, 0.5f);
    p = fmaf(p, u, 1.0f);
    p = fmaf(p, u, 1.0f);
    float tt = p * __int_as_float((e + 127) << 23);
    float l;
    asm("lg2.approx.f32 %0, %1;" : "=f"(l) : "f"(1.0f + tt));
    return fmaxf(s, 0.0f) + 0.69314718055994531f * l;
}

// ---------------------------------------------------------------- init
__global__ void k_init() {
    int idx = blockIdx.x * blockDim.x + threadIdx.x;
    int stride = gridDim.x * blockDim.x;
    for (int i = idx; i < BATCH * DD; i += stride) g_fc[i] = 0.0f;
    uint32_t* xb = (uint32_t*)g_xb;
    for (int i = idx; i < BATCH * KPAD / 2; i += stride) xb[i] = 0u;
    if (idx < NCH) { g_bn1sum[idx] = 0.0; g_bn1sq[idx] = 0.0; }
    if (idx < 4)   g_l2[idx]  = 0.0;
    if (idx < 3)   g_loss[idx] = 0.0;
}

// ------------------------------------------------- fcw L2 + bf16 convert (float4); conv_w L2
__global__ void k_l2w(const float* __restrict__ fcw, const float* __restrict__ cw) {
    __shared__ float sm[8];
    int t = threadIdx.x;
    float loc = 0.0f;
    const float4* src = (const float4*)fcw;
    const int n4 = DD * FCIN / 4;
    for (int i = blockIdx.x * blockDim.x + t; i < n4; i += gridDim.x * blockDim.x) {
        float4 v = src[i];
        loc = fmaf(v.x, v.x, loc); loc = fmaf(v.y, v.y, loc);
        loc = fmaf(v.z, v.z, loc); loc = fmaf(v.w, v.w, loc);
        *(uint2*)&g_fcb[(size_t)i * 4] = make_uint2(bf2pack(v.x, v.y), bf2pack(v.z, v.w));
    }
    loc = warp_red(loc);
    if ((t & 31) == 0) sm[t >> 5] = loc;
    __syncthreads();
    if (t == 0) {
        float S = 0; for (int i = 0; i < 8; i++) S += sm[i];
        atomicAdd(&g_l2[3], (double)S);
    }
    if (blockIdx.x == 0) {
        __syncthreads();
        float lc = 0.0f;
        if (t < NCH * 9) { float v = cw[t]; lc = v * v; }
        lc = warp_red(lc);
        if ((t & 31) == 0) sm[t >> 5] = lc;
        __syncthreads();
        if (t == 0) {
            float S = 0; for (int i = 0; i < 8; i++) S += sm[i];
            atomicAdd(&g_l2[2], (double)S);
        }
    }
}

// ------------------------------------------------- fused gather + emb L2 + conv + bn1 stats
__global__ void k_conv(const float* __restrict__ ew, const float* __restrict__ rw,
                       const int* __restrict__ h, const int* __restrict__ r,
                       const float* __restrict__ cw, const float* __restrict__ g0p) {
    __shared__ float xn[4][400];
    __shared__ float wts[NCH * 9];
    __shared__ float shh[11], shr[11];
    __shared__ float chs[16], chq[16];
    int b0 = blockIdx.x * 4, t = threadIdx.x;
    int c0 = blockIdx.y * 16;
    float g0 = g0p[0];
    float l2h = 0.0f, l2r = 0.0f;
    for (int i = t; i < 1600; i += 352) {
        int bb = i / 400, pos = i % 400, b = b0 + bb;
        float v;
        if (pos < 200) { v = ew[(size_t)h[b] * DD + pos]; l2h = fmaf(v, v, l2h); }
        else           { v = rw[(size_t)r[b] * DD + (pos - 200)]; l2r = fmaf(v, v, l2r); }
        xn[bb][pos] = g0 * v;
    }
    if (t < NCH * 9) wts[t] = cw[t];
    if (t < 16) { chs[t] = 0.0f; chq[t] = 0.0f; }
    if (blockIdx.y == 0) {
        l2h = warp_red(l2h); l2r = warp_red(l2r);
        if ((t & 31) == 0) { shh[t >> 5] = l2h; shr[t >> 5] = l2r; }
    }
    __syncthreads();
    if (blockIdx.y == 0 && t == 0) {
        float H = 0, R = 0;
        for (int i = 0; i < 11; i++) { H += shh[i]; R += shr[i]; }
        atomicAdd(&g_l2[0], (double)H);
        atomicAdd(&g_l2[1], (double)R);
    }
    bool valid = t < 324;
    int ii = valid ? t / 18 : 0;
    int jj = valid ? t % 18 : 0;
    int boff = ii * 20 + jj;
    for (int c = c0; c < c0 + 16; c++) {
        float s = 0.0f, q = 0.0f;
#pragma unroll
        for (int bb = 0; bb < 4; bb++) {
            const float* base = &xn[bb][boff];
            float acc = 0.0f;
#pragma unroll
            for (int ki = 0; ki < 3; ki++)
#pragma unroll
                for (int kj = 0; kj < 3; kj++)
                    acc = fmaf(base[ki * 20 + kj], wts[c * 9 + ki * 3 + kj], acc);
            if (valid) {
                g_conv[((size_t)c * 512 + b0 + bb) * 324 + t] = acc;
                s += acc;
                q = fmaf(acc, acc, q);
            }
        }
        s = warp_red(s); q = warp_red(q);
        if ((t & 31) == 0) { atomicAdd(&chs[c - c0], s); atomicAdd(&chq[c - c0], q); }
    }
    __syncthreads();
    if (t < 16) {
        atomicAdd(&g_bn1sum[c0 + t], (double)chs[t]);
        atomicAdd(&g_bn1sq[c0 + t],  (double)chq[t]);
    }
}

// ------------------------------------------------- bn1 finalize
__global__ void k_bn1fin(const float* __restrict__ g1, const float* __restrict__ b1) {
    int t = threadIdx.x;
    if (t < NCH) {
        double cnt = 512.0 * 324.0;
        double mean = g_bn1sum[t] / cnt;
        double var  = g_bn1sq[t] / cnt - mean * mean;
        float a = g1[t] * rsqrtf((float)var + EPSBN);
        g_a1[t] = a;
        g_b1[t] = b1[t] - (float)mean * a;
    }
}

// ------------------------------------------------- FC via bf16 mma, cp.async pipeline
__global__ __launch_bounds__(256, 2) void k_fc() {
    __shared__ __align__(16) char AB[4][128 * 144];
    __shared__ float a_tab[576], b_tab[576];
    uint32_t as0 = smem_u32(AB[0]);
    uint32_t bs0 = as0 + 2 * 18432;
    int t = threadIdx.x, lane = t & 31, wid = t >> 5;
    int m0 = blockIdx.x * 128, n0 = blockIdx.y * 128;
    int kseg = blockIdx.z * 576;

    for (int i = t; i < 576; i += 256) {
        int c = (kseg + i) / 324;
        a_tab[i] = g_a1[c];
        b_tab[i] = g_b1[c];
    }
    {
#pragma unroll
        for (int j = 0; j < 4; j++) {
            int u = t + j * 256;
            int row = u >> 3, off = u & 7;
            CP_ASYNC16(bs0 + row * 144 + off * 16,
                       (const char*)&g_fcb[(size_t)(n0 + row) * FCIN + kseg + off * 8]);
        }
        CP_COMMIT();
    }
    __syncthreads();

    int mw = wid >> 2, nw = wid & 3;
    int m_base = mw * 64, n_base = nw * 32;
    uint32_t aaddr[4], baddr[2];
#pragma unroll
    for (int mt = 0; mt < 4; mt++)
        aaddr[mt] = as0 + (uint32_t)(m_base + mt * 16 + (lane & 15)) * 144 + (lane >> 4) * 16;
#pragma unroll
    for (int p = 0; p < 2; p++)
        baddr[p] = bs0 + (uint32_t)(n_base + p * 16 + (lane >> 4) * 8 + (lane & 7)) * 144
                       + ((lane >> 3) & 1) * 16;

    float acc[4][4][4];
#pragma unroll
    for (int i = 0; i < 4; i++)
#pragma unroll
        for (int j = 0; j < 4; j++)
#pragma unroll
            for (int k = 0; k < 4; k++) acc[i][j][k] = 0.0f;

    for (int ch = 0; ch < 9; ch++) {
        int buf = ch & 1;
        int kb = kseg + ch * 64;
        {
            int row = t >> 1, half = t & 1;
            char* As = AB[buf];
#pragma unroll
            for (int j = 0; j < 8; j++) {
                int kc = half * 32 + j * 4;
                int kti = ch * 64 + kc;
                int k4 = kb + kc;
                int c = k4 / 324, pp = k4 - c * 324;
                float4 v = *(const float4*)&g_conv[((size_t)c * 512 + m0 + row) * 324 + pp];
                float y0 = fmaxf(fmaf(v.x, a_tab[kti],     b_tab[kti]),     0.0f);
                float y1 = fmaxf(fmaf(v.y, a_tab[kti + 1], b_tab[kti + 1]), 0.0f);
                float y2 = fmaxf(fmaf(v.z, a_tab[kti + 2], b_tab[kti + 2]), 0.0f);
                float y3 = fmaxf(fmaf(v.w, a_tab[kti + 3], b_tab[kti + 3]), 0.0f);
                *(uint2*)&As[row * 144 + kc * 2] = make_uint2(bf2pack(y0, y1), bf2pack(y2, y3));
            }
        }
        CP_WAIT0();
        __syncthreads();
        if (ch < 8) {
            int kb2 = kb + 64;
#pragma unroll
            for (int j = 0; j < 4; j++) {
                int u = t + j * 256;
                int row = u >> 3, off = u & 7;
                CP_ASYNC16(bs0 + (1 - buf) * 18432 + row * 144 + off * 16,
                           (const char*)&g_fcb[(size_t)(n0 + row) * FCIN + kb2 + off * 8]);
            }
            CP_COMMIT();
        }
        uint32_t ao = buf * 18432, bo = buf * 18432;
#pragma unroll
        for (int ks = 0; ks < 4; ks++) {
            uint32_t A[4][4], Bf[2][4];
#pragma unroll
            for (int mt = 0; mt < 4; mt++) ldm4(A[mt], aaddr[mt] + ao + ks * 32);
#pragma unroll
            for (int p = 0; p < 2; p++)   ldm4(Bf[p], baddr[p] + bo + ks * 32);
#pragma unroll
            for (int mt = 0; mt < 4; mt++)
#pragma unroll
                for (int nt = 0; nt < 4; nt++)
                    mma16816(acc[mt][nt], A[mt], &Bf[nt >> 1][(nt & 1) * 2]);
        }
    }
#pragma unroll
    for (int mt = 0; mt < 4; mt++) {
        int r0 = m0 + m_base + mt * 16 + (lane >> 2);
#pragma unroll
        for (int nt = 0; nt < 4; nt++) {
#pragma unroll
            for (int c2 = 0; c2 < 2; c2++) {
                int d = n0 + n_base + nt * 8 + (lane & 3) * 2 + c2;
                if (d < DD) {
                    atomicAdd(&g_fc[r0 * DD + d],       acc[mt][nt][c2]);
                    atomicAdd(&g_fc[(r0 + 8) * DD + d], acc[mt][nt][2 + c2]);
                }
            }
        }
    }
}

// ------------------------------------------------- bn2 + leaky relu -> padded bf16 X image
__global__ void k_bn2(const float* __restrict__ g2, const float* __restrict__ b2) {
    __shared__ float sms[8], smq[8], par[2];
    int d = blockIdx.x, t = threadIdx.x;
    float y0 = g_fc[t * DD + d];
    float y1 = g_fc[(t + 256) * DD + d];
    float s = y0 + y1;
    float q = fmaf(y0, y0, y1 * y1);
    s = warp_red(s); q = warp_red(q);
    if ((t & 31) == 0) { sms[t >> 5] = s; smq[t >> 5] = q; }
    __syncthreads();
    if (t == 0) {
        float S = 0, Q = 0;
        for (int i = 0; i < 8; i++) { S += sms[i]; Q += smq[i]; }
        float mean = S * (1.0f / 512.0f);
        float var  = Q * (1.0f / 512.0f) - mean * mean;
        float a = g2[d] * rsqrtf(var + EPSBN);
        par[0] = a; par[1] = b2[d] - mean * a;
    }
    __syncthreads();
    float a = par[0], c = par[1];
    float v0 = fmaf(y0, a, c); v0 = v0 > 0.0f ? v0 : 0.01f * v0;
    float v1 = fmaf(y1, a, c); v1 = v1 > 0.0f ? v1 : 0.01f * v1;
    g_xb[t * KPAD + d]         = __float2bfloat16_rn(v0);
    g_xb[(t + 256) * KPAD + d] = __float2bfloat16_rn(v1);
    if (blockIdx.x == 0) {                 // bias-fold column: X[:,200] = 1.0
        g_xb[t * KPAD + 200]         = __float2bfloat16_rn(1.0f);
        g_xb[(t + 256) * KPAD + 200] = __float2bfloat16_rn(1.0f);
    }
}

// ------------------------------------------------- positive-target scores (512 dots)
__global__ void k_psx(const float* __restrict__ ew, const float* __restrict__ bias,
                      const int* __restrict__ pos) {
    __shared__ double acc8[8];
    int b = blockIdx.x * 8 + (threadIdx.x >> 5);
    int lane = threadIdx.x & 31;
    int p = pos[b];
    const float* e = ew + (size_t)p * DD;
    float s = 0.0f;
    for (int d = lane; d < DD; d += 32)
        s = fmaf(__bfloat162float(g_xb[b * KPAD + d]), e[d], s);
    s = warp_red(s);
    if (lane == 0) acc8[threadIdx.x >> 5] = (double)(s + bias[p]);
    __syncthreads();
    if (threadIdx.x == 0) {
        double S = 0;
        for (int i = 0; i < 8; i++) S += acc8[i];
        atomicAdd(&g_loss[2], S);
    }
}

// ------------------------------------------------- scores: E once, cp.async X pipeline
// Bias folded into K=200 column; invalid entity rows fully zeroed -> score 0,
// exact softplus(0) correction applied in k_final. Epilogue straight-line.
__global__ __launch_bounds__(256, 2)
void k_scores(const float* __restrict__ ew, const float* __restrict__ bias) {
    extern __shared__ char smem[];
    uint32_t xs = smem_u32(smem);            // X tile: 128 x 216 bf16 = 55296B
    uint32_t es = xs + 55296;                // E tile: 128 x 216 bf16 = 55296B
    __shared__ float red[2][8];
    int t = threadIdx.x, lane = t & 31, wid = t >> 5;
    int NB = blockIdx.x * 128;

    // prefetch X tile 0 while E is loaded/converted
    {
        const char* src = (const char*)g_xb;
        for (int i = t; i < 3456; i += 256) CP_ASYNC16(xs + i * 16, src + i * 16);
        CP_COMMIT();
    }
    char* esm = smem + 55296;
    for (int idx = t; idx < 6400; idx += 256) {
        int row = idx / 50, q = idx % 50;
        int e = NB + row;
        uint2 w = make_uint2(0u, 0u);
        if (e < NENT) {
            float4 v = *(const float4*)&ew[(size_t)e * DD + q * 4];
            w = make_uint2(bf2pack(v.x, v.y), bf2pack(v.z, v.w));
        }
        *(uint2*)(esm + row * 432 + q * 8) = w;
    }
    // cols 200..207: bias at 200, zeros elsewhere
    for (int idx = t; idx < 512; idx += 256) {
        int row = idx >> 2, c = idx & 3;
        uint32_t w = 0u;
        if (c == 0) {
            int e = NB + row;
            if (e < NENT)
                w = (uint32_t)__bfloat16_as_ushort(__float2bfloat16_rn(bias[e]));
        }
        *(uint32_t*)(esm + row * 432 + 400 + c * 4) = w;
    }
    CP_WAIT0();
    __syncthreads();

    int mw = wid >> 2, nw = wid & 3;
    int m_base = mw * 64, n_base = nw * 32;
    uint32_t aaddr[4], baddr[2];
#pragma unroll
    for (int mt = 0; mt < 4; mt++)
        aaddr[mt] = xs + (uint32_t)(m_base + mt * 16 + (lane & 15)) * 432 + (lane >> 4) * 16;
#pragma unroll
    for (int p = 0; p < 2; p++)
        baddr[p] = es + (uint32_t)(n_base + p * 16 + (lane >> 4) * 8 + (lane & 7)) * 432
                      + ((lane >> 3) & 1) * 16;

    float spx = 0.0f, ssx = 0.0f;

    for (int r = 0; r < 4; r++) {
        float acc[4][4][4];
#pragma unroll
        for (int i = 0; i < 4; i++)
#pragma unroll
            for (int j = 0; j < 4; j++)
#pragma unroll
                for (int k = 0; k < 4; k++) acc[i][j][k] = 0.0f;

        for (int ks = 0; ks < 13; ks++) {
            uint32_t A[4][4], Bf[2][4];
#pragma unroll
            for (int mt = 0; mt < 4; mt++) ldm4(A[mt], aaddr[mt] + ks * 32);
#pragma unroll
            for (int p = 0; p < 2; p++)   ldm4(Bf[p], baddr[p] + ks * 32);
#pragma unroll
            for (int mt = 0; mt < 4; mt++)
#pragma unroll
                for (int nt = 0; nt < 4; nt++)
                    mma16816(acc[mt][nt], A[mt], &Bf[nt >> 1][(nt & 1) * 2]);
        }
        __syncthreads();

        if (r < 3) {
            const char* src = (const char*)(g_xb + (r + 1) * 128 * KPAD);
            for (int i = t; i < 3456; i += 256) CP_ASYNC16(xs + i * 16, src + i * 16);
            CP_COMMIT();
        }

        // straight-line epilogue: hybrid softplus + score sum (bias already in GEMM)
#pragma unroll
        for (int mt = 0; mt < 4; mt++)
#pragma unroll
            for (int nt = 0; nt < 4; nt++)
#pragma unroll
                for (int c2 = 0; c2 < 2; c2++) {
                    float s0 = acc[mt][nt][c2];
                    float s1 = acc[mt][nt][2 + c2];
                    spx += softplus_fast(s0) + softplus_fma(s1);
                    ssx += s0 + s1;
                }
        if (r < 3) { CP_WAIT0(); __syncthreads(); }
    }

    spx = warp_red(spx); ssx = warp_red(ssx);
    if (lane == 0) { red[0][wid] = spx; red[1][wid] = ssx; }
    __syncthreads();
    if (t == 0) {
        float SP = 0, SS = 0;
        for (int i = 0; i < 8; i++) { SP += red[0][i]; SS += red[1][i]; }
        atomicAdd(&g_loss[0], (double)SP);
        atomicAdd(&g_loss[1], (double)SS);
    }
}

// ------------------------------------------------- final combine
__global__ void k_final(float* out) {
    double sp = g_loss[0], ss = g_loss[1], ps = g_loss[2];
    // 96 phantom entity rows x 512 batches contribute softplus(0)=ln2 each
    double corr = 49152.0 * 0.69314718055994531;
    double kg = (sp - corr - ss / (double)NENT - 0.9 * ps) / ((double)BATCH * (double)NENT);
    double l2 = g_l2[0] / (2.0 * 512.0 * 200.0)
              + g_l2[1] / (2.0 * 512.0 * 200.0)
              + g_l2[2] / (2.0 * 288.0)
              + g_l2[3] / (2.0 * 200.0);
    out[0] = (float)(kg + 1e-5 * l2);
}

extern "C" void kernel_launch(void* const* d_in, const int* in_sizes, int n_in,
                              void* d_out, int out_size) {
    const float* ew   = (const float*)d_in[0];
    const float* rw   = (const float*)d_in[1];
    const float* cw   = (const float*)d_in[2];
    const float* fcw  = (const float*)d_in[4];
    const float* bias = (const float*)d_in[6];
    const float* g0   = (const float*)d_in[7];
    const float* g1   = (const float*)d_in[9];
    const float* b1   = (const float*)d_in[10];
    const float* g2   = (const float*)d_in[11];
    const float* b2   = (const float*)d_in[12];
    const int*   h    = (const int*)d_in[13];
    const int*   r    = (const int*)d_in[14];
    const int*   pos  = (const int*)d_in[15];

    const int SMEM_SC = 2 * 55296;
    cudaFuncSetAttribute(k_scores, cudaFuncAttributeMaxDynamicSharedMemorySize, SMEM_SC);

    k_init<<<200, 256>>>();
    k_l2w<<<256, 256>>>(fcw, cw);
    k_conv<<<dim3(128, 2), 352>>>(ew, rw, h, r, cw, g0);
    k_bn1fin<<<1, 32>>>(g1, b1);
    k_fc<<<dim3(4, 2, 18), 256>>>();
    k_bn2<<<200, 256>>>(g2, b2);
    k_psx<<<64, 256>>>(ew, bias, pos);
    k_scores<<<782, 256, SMEM_SC>>>(ew, bias);
    k_final<<<1, 1>>>((float*)d_out);
}